// round 2
// baseline (speedup 1.0000x reference)
#include <cuda_runtime.h>
#include <math.h>

#define N_NODES 200000
#define NSEG 1024

// scratch (device globals: no allocation allowed)
__device__ float g_s[N_NODES];        // per-node attention logit
__device__ float g_S[NSEG * 768];     // per-segment per-type sums [seg][t*256+j]
__device__ float g_comb[NSEG * 768];  // [mean | attn | phys]
__device__ float g_h[NSEG * 512];     // hidden after silu
__device__ float g_cnt[NSEG * 3];     // per-type counts (float)

// ---------------------------------------------------------------------------
// K1: s[i] = tanh(x[i]@aw1 + ab1) @ aw2 + ab2  for all nodes.
// Tiled SGEMM 128(nodes) x 128(hidden) x K=256, 256 threads, 8x8 microtile,
// fused tanh + aw2-dot epilogue (shfl reduction) -> writes only s (no H spill).
// ---------------------------------------------------------------------------
__global__ __launch_bounds__(256)
void k1_scores(const float* __restrict__ x, const float* __restrict__ aw1,
               const float* __restrict__ ab1, const float* __restrict__ aw2,
               const float* __restrict__ ab2) {
    __shared__ float As[16][128];
    __shared__ float Bs[16][128];
    int tid = threadIdx.x;
    int m_base = blockIdx.x * 128;

    float acc[8][8];
#pragma unroll
    for (int i = 0; i < 8; i++)
#pragma unroll
        for (int j = 0; j < 8; j++) acc[i][j] = 0.f;

    int m0 = (tid >> 4) << 3;   // node group within tile
    int j0 = (tid & 15) << 3;   // hidden group

    for (int k0 = 0; k0 < 256; k0 += 16) {
        // A tile: 128 rows x 16 k, zero-pad OOB rows
#pragma unroll
        for (int rr = 0; rr < 2; rr++) {
            int m = (tid >> 2) + rr * 64;
            int c = (tid & 3) << 2;
            int gm = m_base + m;
            float4 v = make_float4(0.f, 0.f, 0.f, 0.f);
            if (gm < N_NODES) v = *(const float4*)(x + (size_t)gm * 256 + k0 + c);
            As[c + 0][m] = v.x; As[c + 1][m] = v.y;
            As[c + 2][m] = v.z; As[c + 3][m] = v.w;
        }
        // B tile: aw1 rows k0..k0+15 are contiguous (row-major [256][128])
        {
            const float4* src = (const float4*)(aw1 + k0 * 128);
            float4* dst = (float4*)&Bs[0][0];
            dst[tid]       = src[tid];
            dst[tid + 256] = src[tid + 256];
        }
        __syncthreads();
#pragma unroll
        for (int k = 0; k < 16; k++) {
            float4 a0 = *(const float4*)&As[k][m0];
            float4 a1 = *(const float4*)&As[k][m0 + 4];
            float4 b0 = *(const float4*)&Bs[k][j0];
            float4 b1 = *(const float4*)&Bs[k][j0 + 4];
            float a[8] = {a0.x, a0.y, a0.z, a0.w, a1.x, a1.y, a1.z, a1.w};
            float b[8] = {b0.x, b0.y, b0.z, b0.w, b1.x, b1.y, b1.z, b1.w};
#pragma unroll
            for (int i = 0; i < 8; i++)
#pragma unroll
                for (int j = 0; j < 8; j++)
                    acc[i][j] = fmaf(a[i], b[j], acc[i][j]);
        }
        __syncthreads();
    }

    // epilogue: tanh, dot with aw2 (partial over this thread's 8 hidden units)
    float part[8];
#pragma unroll
    for (int i = 0; i < 8; i++) {
        float p = 0.f;
#pragma unroll
        for (int j = 0; j < 8; j++) {
            float h = tanhf(acc[i][j] + __ldg(ab1 + j0 + j));
            p = fmaf(h, __ldg(aw2 + j0 + j), p);
        }
        part[i] = p;
    }
    // reduce across the 16 lanes sharing one node group (xor net within 16)
#pragma unroll
    for (int i = 0; i < 8; i++) {
#pragma unroll
        for (int o = 1; o < 16; o <<= 1)
            part[i] += __shfl_xor_sync(0xffffffffu, part[i], o);
    }
    if ((tid & 15) == 0) {
        float bb = __ldg(ab2);
#pragma unroll
        for (int i = 0; i < 8; i++) {
            int gm = m_base + m0 + i;
            if (gm < N_NODES) g_s[gm] = part[i] + bb;
        }
    }
}

// ---------------------------------------------------------------------------
// K2: one CTA per segment (batch is sorted -> contiguous ranges).
// Single pass: online softmax (numerator fused), per-type sums, counts.
// Thread j owns channel j (coalesced x reads). Next-iteration operands are
// prefetched so the dependent exp/accumulate chain never waits on DRAM.
// ---------------------------------------------------------------------------
__global__ __launch_bounds__(256)
void k2_pool(const float* __restrict__ x, const int* __restrict__ batch,
             const int* __restrict__ mask) {
    int seg = blockIdx.x;
    int j = threadIdx.x;

    __shared__ int sh_se[2];
    if (j < 2) {
        int target = seg + j;
        int lo = 0, hi = N_NODES;
        while (lo < hi) {
            int mid = (lo + hi) >> 1;
            if (batch[mid] < target) lo = mid + 1; else hi = mid;
        }
        sh_se[j] = lo;
    }
    __syncthreads();
    int start = sh_se[0], end = sh_se[1];

    float m = -1e30f, z = 0.f, acc = 0.f;
    float S0 = 0.f, S1 = 0.f, S2 = 0.f;
    float c0 = 0.f, c1 = 0.f, c2 = 0.f;

    // prefetch pipeline (depth 1)
    float si_n = 0.f, xij_n = 0.f;
    int t1_n = 0, t2_n = 0;
    if (start < end) {
        si_n  = __ldg(g_s + start);
        t1_n  = __ldg(mask + (size_t)start * 3 + 1);
        t2_n  = __ldg(mask + (size_t)start * 3 + 2);
        xij_n = __ldg(x + (size_t)start * 256 + j);
    }

    for (int i = start; i < end; i++) {
        float si = si_n;
        int t1 = t1_n, t2 = t2_n;
        float xij = xij_n;
        int nxt = i + 1;
        if (nxt < end) {
            si_n  = __ldg(g_s + nxt);
            t1_n  = __ldg(mask + (size_t)nxt * 3 + 1);
            t2_n  = __ldg(mask + (size_t)nxt * 3 + 2);
            xij_n = __ldg(x + (size_t)nxt * 256 + j);
        }
        if (si > m) {                 // uniform across CTA (same si)
            float sc = __expf(m - si);
            z *= sc; acc *= sc; m = si;
        }
        float e = __expf(si - m);
        z += e;
        acc = fmaf(e, xij, acc);
        if (t1)      { S1 += xij; c1 += 1.f; }
        else if (t2) { S2 += xij; c2 += 1.f; }
        else         { S0 += xij; c0 += 1.f; }
    }

    float count = (float)(end - start);
    size_t base = (size_t)seg * 768;
    g_comb[base + j]       = (S0 + S1 + S2) / count;   // mean_pool
    g_comb[base + 256 + j] = acc / z;                  // attn_pool
    g_S[base + j]       = S0;
    g_S[base + 256 + j] = S1;
    g_S[base + 512 + j] = S2;
    if (j == 0) {
        g_cnt[seg * 3 + 0] = c0;
        g_cnt[seg * 3 + 1] = c1;
        g_cnt[seg * 3 + 2] = c2;
    }
}

// ---------------------------------------------------------------------------
// Small GEMMs, 64x64x16 tiles, 256 threads, 4x4 microtile.
// EPI==2: phys_pool = [S0 S1 S2] @ [we;wv;wp] + c_t*b_t  -> g_comb[:,512:]
// EPI==1: h = silu(g_comb @ w1 + b1)                      -> g_h
// EPI==0: out = g_h @ w2 + b2                             -> d_out
// ---------------------------------------------------------------------------
template <int EPI>
__global__ __launch_bounds__(256)
void gemm_small(const float* __restrict__ B0, const float* __restrict__ B1,
                const float* __restrict__ B2,
                const float* __restrict__ bias0, const float* __restrict__ bias1,
                const float* __restrict__ bias2, float* __restrict__ Cout) {
    constexpr int K   = (EPI == 0) ? 512 : 768;
    constexpr int lda = (EPI == 0) ? 512 : 768;
    constexpr int ldb = (EPI == 1) ? 512 : 256;
    constexpr int ldc = (EPI == 2) ? 768 : ((EPI == 1) ? 512 : 256);
    constexpr int coff = (EPI == 2) ? 512 : 0;

    const float* A = (EPI == 2) ? g_S : ((EPI == 1) ? g_comb : g_h);
    float* C = (EPI == 2) ? g_comb : ((EPI == 1) ? g_h : Cout);

    __shared__ float As[16][64];
    __shared__ float Bs[16][64];
    int tid = threadIdx.x;
    int m_base = blockIdx.y * 64;
    int n_base = blockIdx.x * 64;

    float acc[4][4];
#pragma unroll
    for (int i = 0; i < 4; i++)
#pragma unroll
        for (int j = 0; j < 4; j++) acc[i][j] = 0.f;

    int m0 = (tid >> 4) << 2;
    int j0 = (tid & 15) << 2;

    for (int k0 = 0; k0 < K; k0 += 16) {
        {
            int m = tid >> 2;
            int c = (tid & 3) << 2;
            float4 v = *(const float4*)(A + (size_t)(m_base + m) * lda + k0 + c);
            As[c + 0][m] = v.x; As[c + 1][m] = v.y;
            As[c + 2][m] = v.z; As[c + 3][m] = v.w;
        }
        {
            int k = tid >> 4;
            int c = (tid & 15) << 2;
            int kk = k0 + k;
            const float* brow;
            if (EPI == 2) {
                brow = (kk < 256) ? (B0 + (size_t)kk * ldb)
                     : (kk < 512) ? (B1 + (size_t)(kk - 256) * ldb)
                                  : (B2 + (size_t)(kk - 512) * ldb);
            } else {
                brow = B0 + (size_t)kk * ldb;
            }
            *(float4*)&Bs[k][c] = *(const float4*)(brow + n_base + c);
        }
        __syncthreads();
#pragma unroll
        for (int k = 0; k < 16; k++) {
            float4 av = *(const float4*)&As[k][m0];
            float4 bv = *(const float4*)&Bs[k][j0];
            float a[4] = {av.x, av.y, av.z, av.w};
            float b[4] = {bv.x, bv.y, bv.z, bv.w};
#pragma unroll
            for (int i = 0; i < 4; i++)
#pragma unroll
                for (int jj = 0; jj < 4; jj++)
                    acc[i][jj] = fmaf(a[i], b[jj], acc[i][jj]);
        }
        __syncthreads();
    }

#pragma unroll
    for (int i = 0; i < 4; i++) {
        int m = m_base + m0 + i;
#pragma unroll
        for (int jj = 0; jj < 4; jj++) {
            int n = n_base + j0 + jj;
            float v = acc[i][jj];
            if (EPI == 0) {
                v += __ldg(bias0 + n);
            } else if (EPI == 1) {
                v += __ldg(bias0 + n);
                v = v / (1.f + __expf(-v));   // silu
            } else {
                v += g_cnt[m * 3 + 0] * __ldg(bias0 + n)
                   + g_cnt[m * 3 + 1] * __ldg(bias1 + n)
                   + g_cnt[m * 3 + 2] * __ldg(bias2 + n);
            }
            C[(size_t)m * ldc + coff + n] = v;
        }
    }
}

// ---------------------------------------------------------------------------
extern "C" void kernel_launch(void* const* d_in, const int* in_sizes, int n_in,
                              void* d_out, int out_size) {
    const float* x    = (const float*)d_in[0];
    const int*   batch = (const int*)d_in[1];
    const int*   mask  = (const int*)d_in[2];
    // d_in[3] = num_segments (fixed 1024)
    const float* aw1 = (const float*)d_in[4];
    const float* ab1 = (const float*)d_in[5];
    const float* aw2 = (const float*)d_in[6];
    const float* ab2 = (const float*)d_in[7];
    const float* we  = (const float*)d_in[8];
    const float* be  = (const float*)d_in[9];
    const float* wv  = (const float*)d_in[10];
    const float* bv  = (const float*)d_in[11];
    const float* wp  = (const float*)d_in[12];
    const float* bp  = (const float*)d_in[13];
    const float* w1  = (const float*)d_in[14];
    const float* b1  = (const float*)d_in[15];
    const float* w2  = (const float*)d_in[16];
    const float* b2  = (const float*)d_in[17];

    k1_scores<<<(N_NODES + 127) / 128, 256>>>(x, aw1, ab1, aw2, ab2);
    k2_pool<<<NSEG, 256>>>(x, batch, mask);
    gemm_small<2><<<dim3(4, 16), 256>>>(we, wv, wp, be, bv, bp, nullptr);
    gemm_small<1><<<dim3(8, 16), 256>>>(w1, nullptr, nullptr, b1, nullptr, nullptr, nullptr);
    gemm_small<0><<<dim3(4, 16), 256>>>(w2, nullptr, nullptr, b2, nullptr, nullptr, (float*)d_out);
}

// round 5
// speedup vs baseline: 1.1189x; 1.1189x over previous
#include <cuda_runtime.h>
#include <math.h>

#define N_NODES 200000
#define NSEG 1024

// scratch (device globals: no allocation allowed)
__device__ float g_s[N_NODES];        // per-node attention logit
__device__ float g_S[NSEG * 768];     // per-segment per-type sums [seg][t*256+j]
__device__ float g_comb[NSEG * 768];  // [mean | attn | phys]
__device__ float g_h[NSEG * 512];     // hidden after silu
__device__ float g_cnt[NSEG * 3];     // per-type counts (float)

// ---- packed f32x2 helpers (sm_100+) --------------------------------------
__device__ __forceinline__ unsigned long long pack2(float lo, float hi) {
    unsigned long long r;
    asm("mov.b64 %0, {%1, %2};" : "=l"(r) : "f"(lo), "f"(hi));
    return r;
}
__device__ __forceinline__ void unpack2(unsigned long long v, float& lo, float& hi) {
    asm("mov.b64 {%0, %1}, %2;" : "=f"(lo), "=f"(hi) : "l"(v));
}
__device__ __forceinline__ void ffma2(unsigned long long& d, unsigned long long a,
                                      unsigned long long b) {
    asm("fma.rn.f32x2 %0, %1, %2, %0;" : "+l"(d) : "l"(a), "l"(b));
}

// ---------------------------------------------------------------------------
// K1: s[i] = tanh(x[i]@aw1 + ab1) @ aw2 + ab2  for all nodes.
// Tiled SGEMM 128x128xK=256, 256 threads, 8x8 microtile computed as 8x4
// packed f32x2 accumulators (FFMA2 = 2 FLOP-pairs per FMA-pipe slot).
// Register prefetch of next global tiles hides DRAM latency across bars.
// ---------------------------------------------------------------------------
__global__ __launch_bounds__(256)
void k1_scores(const float* __restrict__ x, const float* __restrict__ aw1,
               const float* __restrict__ ab1, const float* __restrict__ aw2,
               const float* __restrict__ ab2) {
    __shared__ float As[16][128];
    __shared__ float Bs[16][128];
    int tid = threadIdx.x;
    int m_base = blockIdx.x * 128;

    unsigned long long acc[8][4];
#pragma unroll
    for (int i = 0; i < 8; i++)
#pragma unroll
        for (int j = 0; j < 4; j++) acc[i][j] = 0ull;

    int m0 = (tid >> 4) << 3;   // node group within tile
    int j0 = (tid & 15) << 3;   // hidden group

    // global-load addressing (A: two rows; B: two float4s)
    int am = tid >> 2;            // 0..63
    int ac = (tid & 3) << 2;      // 0,4,8,12

    // prefetch tile k0 = 0
    float4 pa0, pa1, pb0, pb1;
    {
        int gm0 = m_base + am, gm1 = m_base + am + 64;
        pa0 = (gm0 < N_NODES) ? *(const float4*)(x + (size_t)gm0 * 256 + ac)
                              : make_float4(0.f, 0.f, 0.f, 0.f);
        pa1 = (gm1 < N_NODES) ? *(const float4*)(x + (size_t)gm1 * 256 + ac)
                              : make_float4(0.f, 0.f, 0.f, 0.f);
        const float4* src = (const float4*)aw1;
        pb0 = src[tid];
        pb1 = src[tid + 256];
    }

    for (int k0 = 0; k0 < 256; k0 += 16) {
        // store prefetched tile to smem
        As[ac + 0][am] = pa0.x; As[ac + 1][am] = pa0.y;
        As[ac + 2][am] = pa0.z; As[ac + 3][am] = pa0.w;
        As[ac + 0][am + 64] = pa1.x; As[ac + 1][am + 64] = pa1.y;
        As[ac + 2][am + 64] = pa1.z; As[ac + 3][am + 64] = pa1.w;
        {
            float4* dst = (float4*)&Bs[0][0];
            dst[tid] = pb0;
            dst[tid + 256] = pb1;
        }
        __syncthreads();

        // prefetch next tile (overlaps with compute below)
        int kn = k0 + 16;
        if (kn < 256) {
            int gm0 = m_base + am, gm1 = m_base + am + 64;
            pa0 = (gm0 < N_NODES) ? *(const float4*)(x + (size_t)gm0 * 256 + kn + ac)
                                  : make_float4(0.f, 0.f, 0.f, 0.f);
            pa1 = (gm1 < N_NODES) ? *(const float4*)(x + (size_t)gm1 * 256 + kn + ac)
                                  : make_float4(0.f, 0.f, 0.f, 0.f);
            const float4* src = (const float4*)(aw1 + kn * 128);
            pb0 = src[tid];
            pb1 = src[tid + 256];
        }

#pragma unroll
        for (int k = 0; k < 16; k++) {
            float4 a0 = *(const float4*)&As[k][m0];
            float4 a1 = *(const float4*)&As[k][m0 + 4];
            ulonglong2 bv0 = *(const ulonglong2*)&Bs[k][j0];       // pairs (j0,j0+1),(j0+2,j0+3)
            ulonglong2 bv1 = *(const ulonglong2*)&Bs[k][j0 + 4];   // pairs (j0+4..7)
            float a[8] = {a0.x, a0.y, a0.z, a0.w, a1.x, a1.y, a1.z, a1.w};
            unsigned long long bp[4] = {bv0.x, bv0.y, bv1.x, bv1.y};
#pragma unroll
            for (int i = 0; i < 8; i++) {
                unsigned long long ad = pack2(a[i], a[i]);
#pragma unroll
                for (int j = 0; j < 4; j++) ffma2(acc[i][j], ad, bp[j]);
            }
        }
        __syncthreads();
    }

    // epilogue: tanh, dot with aw2 (partial over this thread's 8 hidden units)
    float part[8];
#pragma unroll
    for (int i = 0; i < 8; i++) {
        float p = 0.f;
#pragma unroll
        for (int j = 0; j < 4; j++) {
            float lo, hi;
            unpack2(acc[i][j], lo, hi);
            float h0 = tanhf(lo + __ldg(ab1 + j0 + 2 * j));
            float h1 = tanhf(hi + __ldg(ab1 + j0 + 2 * j + 1));
            p = fmaf(h0, __ldg(aw2 + j0 + 2 * j), p);
            p = fmaf(h1, __ldg(aw2 + j0 + 2 * j + 1), p);
        }
        part[i] = p;
    }
    // reduce across the 16 lanes sharing one node group
#pragma unroll
    for (int i = 0; i < 8; i++) {
#pragma unroll
        for (int o = 1; o < 16; o <<= 1)
            part[i] += __shfl_xor_sync(0xffffffffu, part[i], o);
    }
    if ((tid & 15) == 0) {
        float bb = __ldg(ab2);
#pragma unroll
        for (int i = 0; i < 8; i++) {
            int gm = m_base + m0 + i;
            if (gm < N_NODES) g_s[gm] = part[i] + bb;
        }
    }
}

// ---------------------------------------------------------------------------
// K2: one CTA per segment (batch is sorted -> contiguous ranges).
// Single pass: online softmax (numerator fused), per-type sums, counts.
// Thread j owns channel j (coalesced x reads); depth-1 prefetch.
// ---------------------------------------------------------------------------
__global__ __launch_bounds__(256)
void k2_pool(const float* __restrict__ x, const int* __restrict__ batch,
             const int* __restrict__ mask) {
    int seg = blockIdx.x;
    int j = threadIdx.x;

    __shared__ int sh_se[2];
    if (j < 2) {
        int target = seg + j;
        int lo = 0, hi = N_NODES;
        while (lo < hi) {
            int mid = (lo + hi) >> 1;
            if (batch[mid] < target) lo = mid + 1; else hi = mid;
        }
        sh_se[j] = lo;
    }
    __syncthreads();
    int start = sh_se[0], end = sh_se[1];

    float m = -1e30f, z = 0.f, acc = 0.f;
    float S0 = 0.f, S1 = 0.f, S2 = 0.f;
    float c0 = 0.f, c1 = 0.f, c2 = 0.f;

    float si_n = 0.f, xij_n = 0.f;
    int t1_n = 0, t2_n = 0;
    if (start < end) {
        si_n  = __ldg(g_s + start);
        t1_n  = __ldg(mask + (size_t)start * 3 + 1);
        t2_n  = __ldg(mask + (size_t)start * 3 + 2);
        xij_n = __ldg(x + (size_t)start * 256 + j);
    }

    for (int i = start; i < end; i++) {
        float si = si_n;
        int t1 = t1_n, t2 = t2_n;
        float xij = xij_n;
        int nxt = i + 1;
        if (nxt < end) {
            si_n  = __ldg(g_s + nxt);
            t1_n  = __ldg(mask + (size_t)nxt * 3 + 1);
            t2_n  = __ldg(mask + (size_t)nxt * 3 + 2);
            xij_n = __ldg(x + (size_t)nxt * 256 + j);
        }
        if (si > m) {                 // uniform across CTA (same si)
            float sc = __expf(m - si);
            z *= sc; acc *= sc; m = si;
        }
        float e = __expf(si - m);
        z += e;
        acc = fmaf(e, xij, acc);
        if (t1)      { S1 += xij; c1 += 1.f; }
        else if (t2) { S2 += xij; c2 += 1.f; }
        else         { S0 += xij; c0 += 1.f; }
    }

    float count = (float)(end - start);
    size_t base = (size_t)seg * 768;
    g_comb[base + j]       = (S0 + S1 + S2) / count;   // mean_pool
    g_comb[base + 256 + j] = acc / z;                  // attn_pool
    g_S[base + j]       = S0;
    g_S[base + 256 + j] = S1;
    g_S[base + 512 + j] = S2;
    if (j == 0) {
        g_cnt[seg * 3 + 0] = c0;
        g_cnt[seg * 3 + 1] = c1;
        g_cnt[seg * 3 + 2] = c2;
    }
}

// ---------------------------------------------------------------------------
// Small GEMMs, 64x64x16 tiles, 256 threads, 4x4 microtile, register
// double-buffered global loads (prefetch k+1 before compute on k).
// EPI==2: phys_pool = [S0 S1 S2] @ [we;wv;wp] + c_t*b_t  -> g_comb[:,512:]
// EPI==1: h = silu(g_comb @ w1 + b1)                      -> g_h
// EPI==0: out = g_h @ w2 + b2                             -> d_out
// ---------------------------------------------------------------------------
template <int EPI>
__global__ __launch_bounds__(256)
void gemm_small(const float* __restrict__ B0, const float* __restrict__ B1,
                const float* __restrict__ B2,
                const float* __restrict__ bias0, const float* __restrict__ bias1,
                const float* __restrict__ bias2, float* __restrict__ Cout) {
    constexpr int K   = (EPI == 0) ? 512 : 768;
    constexpr int lda = (EPI == 0) ? 512 : 768;
    constexpr int ldb = (EPI == 1) ? 512 : 256;
    constexpr int ldc = (EPI == 2) ? 768 : ((EPI == 1) ? 512 : 256);
    constexpr int coff = (EPI == 2) ? 512 : 0;

    const float* A = (EPI == 2) ? g_S : ((EPI == 1) ? g_comb : g_h);
    float* C = (EPI == 2) ? g_comb : ((EPI == 1) ? g_h : Cout);

    __shared__ float As[16][64];
    __shared__ float Bs[16][64];
    int tid = threadIdx.x;
    int m_base = blockIdx.y * 64;
    int n_base = blockIdx.x * 64;

    float acc[4][4];
#pragma unroll
    for (int i = 0; i < 4; i++)
#pragma unroll
        for (int j = 0; j < 4; j++) acc[i][j] = 0.f;

    int m0 = (tid >> 4) << 2;
    int j0 = (tid & 15) << 2;

    // addressing for loads
    int am = tid >> 2, ac = (tid & 3) << 2;           // A: row am, k-chunk ac
    int bk = tid >> 4, bc = (tid & 15) << 2;          // B: k-row bk, col-chunk bc

    auto brow_ptr = [&](int kk) -> const float* {
        if (EPI == 2) {
            return (kk < 256) ? (B0 + (size_t)kk * ldb)
                 : (kk < 512) ? (B1 + (size_t)(kk - 256) * ldb)
                              : (B2 + (size_t)(kk - 512) * ldb);
        }
        return B0 + (size_t)kk * ldb;
    };

    float4 pa = *(const float4*)(A + (size_t)(m_base + am) * lda + ac);
    float4 pb = *(const float4*)(brow_ptr(bk) + n_base + bc);

    for (int k0 = 0; k0 < K; k0 += 16) {
        As[ac + 0][am] = pa.x; As[ac + 1][am] = pa.y;
        As[ac + 2][am] = pa.z; As[ac + 3][am] = pa.w;
        *(float4*)&Bs[bk][bc] = pb;
        __syncthreads();

        int kn = k0 + 16;
        if (kn < K) {
            pa = *(const float4*)(A + (size_t)(m_base + am) * lda + kn + ac);
            pb = *(const float4*)(brow_ptr(kn + bk) + n_base + bc);
        }

#pragma unroll
        for (int k = 0; k < 16; k++) {
            float4 av = *(const float4*)&As[k][m0];
            float4 bv = *(const float4*)&Bs[k][j0];
            float a[4] = {av.x, av.y, av.z, av.w};
            float b[4] = {bv.x, bv.y, bv.z, bv.w};
#pragma unroll
            for (int i = 0; i < 4; i++)
#pragma unroll
                for (int jj = 0; jj < 4; jj++)
                    acc[i][jj] = fmaf(a[i], b[jj], acc[i][jj]);
        }
        __syncthreads();
    }

#pragma unroll
    for (int i = 0; i < 4; i++) {
        int m = m_base + m0 + i;
#pragma unroll
        for (int jj = 0; jj < 4; jj++) {
            int n = n_base + j0 + jj;
            float v = acc[i][jj];
            if (EPI == 0) {
                v += __ldg(bias0 + n);
            } else if (EPI == 1) {
                v += __ldg(bias0 + n);
                v = v / (1.f + __expf(-v));   // silu
            } else {
                v += g_cnt[m * 3 + 0] * __ldg(bias0 + n)
                   + g_cnt[m * 3 + 1] * __ldg(bias1 + n)
                   + g_cnt[m * 3 + 2] * __ldg(bias2 + n);
            }
            C[(size_t)m * ldc + coff + n] = v;
        }
    }
}

// ---------------------------------------------------------------------------
extern "C" void kernel_launch(void* const* d_in, const int* in_sizes, int n_in,
                              void* d_out, int out_size) {
    const float* x    = (const float*)d_in[0];
    const int*   batch = (const int*)d_in[1];
    const int*   mask  = (const int*)d_in[2];
    // d_in[3] = num_segments (fixed 1024)
    const float* aw1 = (const float*)d_in[4];
    const float* ab1 = (const float*)d_in[5];
    const float* aw2 = (const float*)d_in[6];
    const float* ab2 = (const float*)d_in[7];
    const float* we  = (const float*)d_in[8];
    const float* be  = (const float*)d_in[9];
    const float* wv  = (const float*)d_in[10];
    const float* bv  = (const float*)d_in[11];
    const float* wp  = (const float*)d_in[12];
    const float* bp  = (const float*)d_in[13];
    const float* w1  = (const float*)d_in[14];
    const float* b1  = (const float*)d_in[15];
    const float* w2  = (const float*)d_in[16];
    const float* b2  = (const float*)d_in[17];

    k1_scores<<<(N_NODES + 127) / 128, 256>>>(x, aw1, ab1, aw2, ab2);
    k2_pool<<<NSEG, 256>>>(x, batch, mask);
    gemm_small<2><<<dim3(4, 16), 256>>>(we, wv, wp, be, bv, bp, nullptr);
    gemm_small<1><<<dim3(8, 16), 256>>>(w1, nullptr, nullptr, b1, nullptr, nullptr, nullptr);
    gemm_small<0><<<dim3(4, 16), 256>>>(w2, nullptr, nullptr, b2, nullptr, nullptr, (float*)d_out);
}

// round 6
// speedup vs baseline: 1.1341x; 1.0136x over previous
#include <cuda_runtime.h>
#include <cuda_bf16.h>
#include <math.h>

#define N_NODES 200000
#define NSEG 1024
#define KP 40   // smem k-pitch (bf16 elems) -> conflict-free fragment LDS

// scratch (device globals: no allocation allowed)
__device__ float g_s[N_NODES];        // per-node attention logit
__device__ float g_S[NSEG * 768];     // per-segment per-type sums
__device__ float g_comb[NSEG * 768];  // [mean | attn | phys]
__device__ float g_h[NSEG * 512];     // hidden after silu
__device__ float g_cnt[NSEG * 3];     // per-type counts

// ---- warp mma m16n8k16 bf16 ----------------------------------------------
__device__ __forceinline__ void mma16816(float* d, const unsigned* a,
                                         const unsigned* b) {
    asm volatile(
        "mma.sync.aligned.m16n8k16.row.col.f32.bf16.bf16.f32 "
        "{%0,%1,%2,%3}, {%4,%5,%6,%7}, {%8,%9}, {%0,%1,%2,%3};"
        : "+f"(d[0]), "+f"(d[1]), "+f"(d[2]), "+f"(d[3])
        : "r"(a[0]), "r"(a[1]), "r"(a[2]), "r"(a[3]), "r"(b[0]), "r"(b[1]));
}

// ---------------------------------------------------------------------------
// K1: s[i] = tanh(x[i]@aw1 + ab1) @ aw2 + ab2, tensor-core path.
// CTA tile 128(M) x 128(N), K-chunks of 32. bf16 hi/lo split of both x and
// aw1; 3 MMAs per product give ~fp32 accuracy with fp32 accumulators.
// 8 warps in a 4(M) x 2(N) grid, warp tile 32 x 64.
// ---------------------------------------------------------------------------
__global__ __launch_bounds__(256)
void k1_scores(const float* __restrict__ x, const float* __restrict__ aw1,
               const float* __restrict__ ab1, const float* __restrict__ aw2,
               const float* __restrict__ ab2) {
    __shared__ __nv_bfloat16 Ah[128 * KP], Al[128 * KP];
    __shared__ __nv_bfloat16 Bh[128 * KP], Bl[128 * KP];
    __shared__ float red[8][32];

    int tid = threadIdx.x;
    int warp = tid >> 5, lane = tid & 31;
    int g = lane >> 2, tg = lane & 3;
    int mw = warp >> 1, nw = warp & 1;
    int warp_m = mw * 32, warp_n = nw * 64;
    int m_base = blockIdx.x * 128;

    float acc[2][8][4];
#pragma unroll
    for (int a = 0; a < 2; a++)
#pragma unroll
        for (int b = 0; b < 8; b++)
#pragma unroll
            for (int c = 0; c < 4; c++) acc[a][b][c] = 0.f;

    for (int k0 = 0; k0 < 256; k0 += 32) {
        // x chunk [128 m][32 k] -> Ah/Al (hi/lo bf16 split), [m][k] layout
#pragma unroll
        for (int i = 0; i < 4; i++) {
            int idx = tid + i * 256;        // 0..1023
            int row = idx >> 3;             // 0..127
            int c4 = idx & 7;               // float4 col in chunk
            int gm = m_base + row;
            float4 v = (gm < N_NODES)
                           ? *(const float4*)(x + (size_t)gm * 256 + k0 + c4 * 4)
                           : make_float4(0.f, 0.f, 0.f, 0.f);
            float vv[4] = {v.x, v.y, v.z, v.w};
            __nv_bfloat16 h[4], l[4];
#pragma unroll
            for (int e = 0; e < 4; e++) {
                h[e] = __float2bfloat16_rn(vv[e]);
                l[e] = __float2bfloat16_rn(vv[e] - __bfloat162float(h[e]));
            }
            int off = row * KP + c4 * 4;
            *(uint2*)&Ah[off] = *(uint2*)h;
            *(uint2*)&Al[off] = *(uint2*)l;
        }
        // aw1 chunk rows k0..k0+31 of [256][128] -> Bh/Bl transposed [n][k]
#pragma unroll
        for (int i = 0; i < 4; i++) {
            int idx = tid + i * 256;
            int k = idx >> 5;               // 0..31
            int c4 = idx & 31;              // n float4
            float4 v = *(const float4*)(aw1 + (size_t)(k0 + k) * 128 + c4 * 4);
            float vv[4] = {v.x, v.y, v.z, v.w};
#pragma unroll
            for (int e = 0; e < 4; e++) {
                int n = c4 * 4 + e;
                __nv_bfloat16 hh = __float2bfloat16_rn(vv[e]);
                Bh[n * KP + k] = hh;
                Bl[n * KP + k] = __float2bfloat16_rn(vv[e] - __bfloat162float(hh));
            }
        }
        __syncthreads();

#pragma unroll
        for (int kb = 0; kb < 2; kb++) {
            int kk = kb * 16 + tg * 2;
            unsigned ah[2][4], al[2][4];
#pragma unroll
            for (int mb = 0; mb < 2; mb++) {
                int r = warp_m + mb * 16;
                ah[mb][0] = *(const unsigned*)&Ah[(r + g) * KP + kk];
                ah[mb][1] = *(const unsigned*)&Ah[(r + g + 8) * KP + kk];
                ah[mb][2] = *(const unsigned*)&Ah[(r + g) * KP + kk + 8];
                ah[mb][3] = *(const unsigned*)&Ah[(r + g + 8) * KP + kk + 8];
                al[mb][0] = *(const unsigned*)&Al[(r + g) * KP + kk];
                al[mb][1] = *(const unsigned*)&Al[(r + g + 8) * KP + kk];
                al[mb][2] = *(const unsigned*)&Al[(r + g) * KP + kk + 8];
                al[mb][3] = *(const unsigned*)&Al[(r + g + 8) * KP + kk + 8];
            }
#pragma unroll
            for (int nb = 0; nb < 8; nb++) {
                int n = warp_n + nb * 8 + g;
                unsigned bh[2], bl[2];
                bh[0] = *(const unsigned*)&Bh[n * KP + kk];
                bh[1] = *(const unsigned*)&Bh[n * KP + kk + 8];
                bl[0] = *(const unsigned*)&Bl[n * KP + kk];
                bl[1] = *(const unsigned*)&Bl[n * KP + kk + 8];
#pragma unroll
                for (int mb = 0; mb < 2; mb++) {
                    mma16816(acc[mb][nb], ah[mb], bh);
                    mma16816(acc[mb][nb], ah[mb], bl);
                    mma16816(acc[mb][nb], al[mb], bh);
                }
            }
        }
        __syncthreads();
    }

    // epilogue: tanh + dot with aw2, per-row reduction
    float p[2][2] = {{0.f, 0.f}, {0.f, 0.f}};   // [mb][row-half]
#pragma unroll
    for (int mb = 0; mb < 2; mb++) {
#pragma unroll
        for (int nb = 0; nb < 8; nb++) {
            int n0 = warp_n + nb * 8 + tg * 2;
            float w0 = __ldg(aw2 + n0), w1 = __ldg(aw2 + n0 + 1);
            float bb0 = __ldg(ab1 + n0), bb1 = __ldg(ab1 + n0 + 1);
            p[mb][0] = fmaf(tanhf(acc[mb][nb][0] + bb0), w0, p[mb][0]);
            p[mb][0] = fmaf(tanhf(acc[mb][nb][1] + bb1), w1, p[mb][0]);
            p[mb][1] = fmaf(tanhf(acc[mb][nb][2] + bb0), w1 * 0.f + w0, p[mb][1]);
            p[mb][1] = fmaf(tanhf(acc[mb][nb][3] + bb1), w1, p[mb][1]);
        }
    }
    // reduce across the 4 lanes (tg) sharing each row
#pragma unroll
    for (int mb = 0; mb < 2; mb++)
#pragma unroll
        for (int h = 0; h < 2; h++) {
            p[mb][h] += __shfl_xor_sync(0xffffffffu, p[mb][h], 1);
            p[mb][h] += __shfl_xor_sync(0xffffffffu, p[mb][h], 2);
        }
    if (tg == 0) {
#pragma unroll
        for (int mb = 0; mb < 2; mb++) {
            red[warp][mb * 16 + g] = p[mb][0];
            red[warp][mb * 16 + g + 8] = p[mb][1];
        }
    }
    __syncthreads();
    if (tid < 128) {
        int row = tid;
        int mwi = row >> 5, rl = row & 31;
        float v = red[mwi * 2][rl] + red[mwi * 2 + 1][rl] + __ldg(ab2);
        int gm = m_base + row;
        if (gm < N_NODES) g_s[gm] = v;
    }
}

// ---------------------------------------------------------------------------
// K2: one CTA per segment (batch sorted -> contiguous ranges).
// ---------------------------------------------------------------------------
__global__ __launch_bounds__(256)
void k2_pool(const float* __restrict__ x, const int* __restrict__ batch,
             const int* __restrict__ mask) {
    int seg = blockIdx.x;
    int j = threadIdx.x;

    __shared__ int sh_se[2];
    if (j < 2) {
        int target = seg + j;
        int lo = 0, hi = N_NODES;
        while (lo < hi) {
            int mid = (lo + hi) >> 1;
            if (batch[mid] < target) lo = mid + 1; else hi = mid;
        }
        sh_se[j] = lo;
    }
    __syncthreads();
    int start = sh_se[0], end = sh_se[1];

    float m = -1e30f, z = 0.f, acc = 0.f;
    float S0 = 0.f, S1 = 0.f, S2 = 0.f;
    float c0 = 0.f, c1 = 0.f, c2 = 0.f;

    float si_n = 0.f, xij_n = 0.f;
    int t1_n = 0, t2_n = 0;
    if (start < end) {
        si_n  = __ldg(g_s + start);
        t1_n  = __ldg(mask + (size_t)start * 3 + 1);
        t2_n  = __ldg(mask + (size_t)start * 3 + 2);
        xij_n = __ldg(x + (size_t)start * 256 + j);
    }

    for (int i = start; i < end; i++) {
        float si = si_n;
        int t1 = t1_n, t2 = t2_n;
        float xij = xij_n;
        int nxt = i + 1;
        if (nxt < end) {
            si_n  = __ldg(g_s + nxt);
            t1_n  = __ldg(mask + (size_t)nxt * 3 + 1);
            t2_n  = __ldg(mask + (size_t)nxt * 3 + 2);
            xij_n = __ldg(x + (size_t)nxt * 256 + j);
        }
        if (si > m) {
            float sc = __expf(m - si);
            z *= sc; acc *= sc; m = si;
        }
        float e = __expf(si - m);
        z += e;
        acc = fmaf(e, xij, acc);
        if (t1)      { S1 += xij; c1 += 1.f; }
        else if (t2) { S2 += xij; c2 += 1.f; }
        else         { S0 += xij; c0 += 1.f; }
    }

    float count = (float)(end - start);
    size_t base = (size_t)seg * 768;
    g_comb[base + j]       = (S0 + S1 + S2) / count;
    g_comb[base + 256 + j] = acc / z;
    g_S[base + j]       = S0;
    g_S[base + 256 + j] = S1;
    g_S[base + 512 + j] = S2;
    if (j == 0) {
        g_cnt[seg * 3 + 0] = c0;
        g_cnt[seg * 3 + 1] = c1;
        g_cnt[seg * 3 + 2] = c2;
    }
}

// ---------------------------------------------------------------------------
// Small GEMMs, 64x64x16 tiles, 256 threads, 4x4 microtile, register
// double-buffered global loads.
// ---------------------------------------------------------------------------
template <int EPI>
__global__ __launch_bounds__(256)
void gemm_small(const float* __restrict__ B0, const float* __restrict__ B1,
                const float* __restrict__ B2,
                const float* __restrict__ bias0, const float* __restrict__ bias1,
                const float* __restrict__ bias2, float* __restrict__ Cout) {
    constexpr int K   = (EPI == 0) ? 512 : 768;
    constexpr int lda = (EPI == 0) ? 512 : 768;
    constexpr int ldb = (EPI == 1) ? 512 : 256;
    constexpr int ldc = (EPI == 2) ? 768 : ((EPI == 1) ? 512 : 256);
    constexpr int coff = (EPI == 2) ? 512 : 0;

    const float* A = (EPI == 2) ? g_S : ((EPI == 1) ? g_comb : g_h);
    float* C = (EPI == 2) ? g_comb : ((EPI == 1) ? g_h : Cout);

    __shared__ float As[16][64];
    __shared__ float Bs[16][64];
    int tid = threadIdx.x;
    int m_base = blockIdx.y * 64;
    int n_base = blockIdx.x * 64;

    float acc[4][4];
#pragma unroll
    for (int i = 0; i < 4; i++)
#pragma unroll
        for (int j = 0; j < 4; j++) acc[i][j] = 0.f;

    int m0 = (tid >> 4) << 2;
    int j0 = (tid & 15) << 2;

    int am = tid >> 2, ac = (tid & 3) << 2;
    int bk = tid >> 4, bc = (tid & 15) << 2;

    auto brow_ptr = [&](int kk) -> const float* {
        if (EPI == 2) {
            return (kk < 256) ? (B0 + (size_t)kk * ldb)
                 : (kk < 512) ? (B1 + (size_t)(kk - 256) * ldb)
                              : (B2 + (size_t)(kk - 512) * ldb);
        }
        return B0 + (size_t)kk * ldb;
    };

    float4 pa = *(const float4*)(A + (size_t)(m_base + am) * lda + ac);
    float4 pb = *(const float4*)(brow_ptr(bk) + n_base + bc);

    for (int k0 = 0; k0 < K; k0 += 16) {
        As[ac + 0][am] = pa.x; As[ac + 1][am] = pa.y;
        As[ac + 2][am] = pa.z; As[ac + 3][am] = pa.w;
        *(float4*)&Bs[bk][bc] = pb;
        __syncthreads();

        int kn = k0 + 16;
        if (kn < K) {
            pa = *(const float4*)(A + (size_t)(m_base + am) * lda + kn + ac);
            pb = *(const float4*)(brow_ptr(kn + bk) + n_base + bc);
        }

#pragma unroll
        for (int k = 0; k < 16; k++) {
            float4 av = *(const float4*)&As[k][m0];
            float4 bv = *(const float4*)&Bs[k][j0];
            float a[4] = {av.x, av.y, av.z, av.w};
            float b[4] = {bv.x, bv.y, bv.z, bv.w};
#pragma unroll
            for (int i = 0; i < 4; i++)
#pragma unroll
                for (int jj = 0; jj < 4; jj++)
                    acc[i][jj] = fmaf(a[i], b[jj], acc[i][jj]);
        }
        __syncthreads();
    }

#pragma unroll
    for (int i = 0; i < 4; i++) {
        int m = m_base + m0 + i;
#pragma unroll
        for (int jj = 0; jj < 4; jj++) {
            int n = n_base + j0 + jj;
            float v = acc[i][jj];
            if (EPI == 0) {
                v += __ldg(bias0 + n);
            } else if (EPI == 1) {
                v += __ldg(bias0 + n);
                v = v / (1.f + __expf(-v));   // silu
            } else {
                v += g_cnt[m * 3 + 0] * __ldg(bias0 + n)
                   + g_cnt[m * 3 + 1] * __ldg(bias1 + n)
                   + g_cnt[m * 3 + 2] * __ldg(bias2 + n);
            }
            C[(size_t)m * ldc + coff + n] = v;
        }
    }
}

// ---------------------------------------------------------------------------
extern "C" void kernel_launch(void* const* d_in, const int* in_sizes, int n_in,
                              void* d_out, int out_size) {
    const float* x    = (const float*)d_in[0];
    const int*   batch = (const int*)d_in[1];
    const int*   mask  = (const int*)d_in[2];
    const float* aw1 = (const float*)d_in[4];
    const float* ab1 = (const float*)d_in[5];
    const float* aw2 = (const float*)d_in[6];
    const float* ab2 = (const float*)d_in[7];
    const float* we  = (const float*)d_in[8];
    const float* be  = (const float*)d_in[9];
    const float* wv  = (const float*)d_in[10];
    const float* bv  = (const float*)d_in[11];
    const float* wp  = (const float*)d_in[12];
    const float* bp  = (const float*)d_in[13];
    const float* w1  = (const float*)d_in[14];
    const float* b1  = (const float*)d_in[15];
    const float* w2  = (const float*)d_in[16];
    const float* b2  = (const float*)d_in[17];

    k1_scores<<<(N_NODES + 127) / 128, 256>>>(x, aw1, ab1, aw2, ab2);
    k2_pool<<<NSEG, 256>>>(x, batch, mask);
    gemm_small<2><<<dim3(4, 16), 256>>>(we, wv, wp, be, bv, bp, nullptr);
    gemm_small<1><<<dim3(8, 16), 256>>>(w1, nullptr, nullptr, b1, nullptr, nullptr, nullptr);
    gemm_small<0><<<dim3(4, 16), 256>>>(w2, nullptr, nullptr, b2, nullptr, nullptr, (float*)d_out);
}

// round 7
// speedup vs baseline: 1.5344x; 1.3530x over previous
#include <cuda_runtime.h>
#include <cuda_bf16.h>
#include <math.h>

#define N_NODES 200000
#define NSEG 1024
#define KP 40   // smem k-pitch (bf16 elems) -> conflict-free fragment LDS

// scratch (device globals: no allocation allowed)
__device__ float g_s[N_NODES];
__device__ float g_S[NSEG * 768];
__device__ float g_comb[NSEG * 768];
__device__ float g_h[NSEG * 512];
__device__ float g_cnt[NSEG * 3];
__device__ __nv_bfloat16 g_Bh[128 * 256];   // aw1 hi, transposed [n][k]
__device__ __nv_bfloat16 g_Bl[128 * 256];   // aw1 lo, transposed [n][k]

// ---- warp mma m16n8k16 bf16 ----------------------------------------------
__device__ __forceinline__ void mma16816(float* d, const unsigned* a,
                                         const unsigned* b) {
    asm volatile(
        "mma.sync.aligned.m16n8k16.row.col.f32.bf16.bf16.f32 "
        "{%0,%1,%2,%3}, {%4,%5,%6,%7}, {%8,%9}, {%0,%1,%2,%3};"
        : "+f"(d[0]), "+f"(d[1]), "+f"(d[2]), "+f"(d[3])
        : "r"(a[0]), "r"(a[1]), "r"(a[2]), "r"(a[3]), "r"(b[0]), "r"(b[1]));
}

// ---------------------------------------------------------------------------
// K0: one-time hi/lo bf16 split of aw1, transposed to [n][k].
// ---------------------------------------------------------------------------
__global__ __launch_bounds__(256)
void k0_wsplit(const float* __restrict__ aw1) {
    int idx = blockIdx.x * 256 + threadIdx.x;   // 0..32767
    int k = idx >> 7, n = idx & 127;
    float v = aw1[(size_t)k * 128 + n];
    __nv_bfloat16 h = __float2bfloat16_rn(v);
    g_Bh[n * 256 + k] = h;
    g_Bl[n * 256 + k] = __float2bfloat16_rn(v - __bfloat162float(h));
}

// ---------------------------------------------------------------------------
// K1: s[i] = tanh(x[i]@aw1 + ab1) @ aw2 + ab2, tensor-core path.
// CTA tile 128(M) x 128(N); K in 8 chunks of 32; double-buffered smem with
// register prefetch: global loads for chunk c+1 issue before MMA(c), the
// x hi/lo conversion runs after MMA(c), one syncthreads per chunk.
// B (aw1 split) comes preconverted from g_Bh/g_Bl.
// Dynamic smem layout per buffer (bf16 elems): Ah[5120] Al[5120] Bh[5120] Bl[5120].
// ---------------------------------------------------------------------------
__global__ __launch_bounds__(256)
void k1_scores(const float* __restrict__ x, const float* __restrict__ ab1,
               const float* __restrict__ aw2, const float* __restrict__ ab2) {
    extern __shared__ __align__(16) __nv_bfloat16 sm[];
    __shared__ float red[8][32];

    int tid = threadIdx.x;
    int warp = tid >> 5, lane = tid & 31;
    int g = lane >> 2, tg = lane & 3;
    int warp_m = (warp >> 1) * 32, warp_n = (warp & 1) * 64;
    int m_base = blockIdx.x * 128;

    float acc[2][8][4];
#pragma unroll
    for (int a = 0; a < 2; a++)
#pragma unroll
        for (int b = 0; b < 8; b++)
#pragma unroll
            for (int c = 0; c < 4; c++) acc[a][b][c] = 0.f;

    // prefetch registers
    float4 pa[4];
    uint4 pbh[2], pbl[2];

    int bn = tid >> 1, bj = (tid & 1) * 2;   // B staging: row bn, 16B blocks bj,bj+1

    auto loadA = [&](int k0) {
#pragma unroll
        for (int i = 0; i < 4; i++) {
            int idx = tid + i * 256;
            int row = idx >> 3, c4 = idx & 7;
            int gm = m_base + row;
            pa[i] = (gm < N_NODES)
                        ? *(const float4*)(x + (size_t)gm * 256 + k0 + c4 * 4)
                        : make_float4(0.f, 0.f, 0.f, 0.f);
        }
    };
    auto loadB = [&](int k0) {
#pragma unroll
        for (int j = 0; j < 2; j++) {
            pbh[j] = *(const uint4*)(g_Bh + bn * 256 + k0 + (bj + j) * 8);
            pbl[j] = *(const uint4*)(g_Bl + bn * 256 + k0 + (bj + j) * 8);
        }
    };
    auto convStore = [&](int buf) {
        __nv_bfloat16* Ah = sm + buf * 20480;
        __nv_bfloat16* Al = Ah + 5120;
        __nv_bfloat16* Bh = Ah + 10240;
        __nv_bfloat16* Bl = Ah + 15360;
#pragma unroll
        for (int i = 0; i < 4; i++) {
            int idx = tid + i * 256;
            int row = idx >> 3, c4 = idx & 7;
            float4 v = pa[i];
            __nv_bfloat162 h01 = __floats2bfloat162_rn(v.x, v.y);
            __nv_bfloat162 h23 = __floats2bfloat162_rn(v.z, v.w);
            float r0 = v.x - __low2float(h01), r1 = v.y - __high2float(h01);
            float r2 = v.z - __low2float(h23), r3 = v.w - __high2float(h23);
            __nv_bfloat162 l01 = __floats2bfloat162_rn(r0, r1);
            __nv_bfloat162 l23 = __floats2bfloat162_rn(r2, r3);
            int off = row * KP + c4 * 4;
            *(uint2*)&Ah[off] = make_uint2(*(unsigned*)&h01, *(unsigned*)&h23);
            *(uint2*)&Al[off] = make_uint2(*(unsigned*)&l01, *(unsigned*)&l23);
        }
#pragma unroll
        for (int j = 0; j < 2; j++) {
            *(uint4*)&Bh[bn * KP + (bj + j) * 8] = pbh[j];
            *(uint4*)&Bl[bn * KP + (bj + j) * 8] = pbl[j];
        }
    };
    auto mmaChunk = [&](int buf) {
        const __nv_bfloat16* Ah = sm + buf * 20480;
        const __nv_bfloat16* Al = Ah + 5120;
        const __nv_bfloat16* Bh = Ah + 10240;
        const __nv_bfloat16* Bl = Ah + 15360;
#pragma unroll
        for (int kb = 0; kb < 2; kb++) {
            int kk = kb * 16 + tg * 2;
            unsigned ah[2][4], al[2][4];
#pragma unroll
            for (int mb = 0; mb < 2; mb++) {
                int r = warp_m + mb * 16;
                ah[mb][0] = *(const unsigned*)&Ah[(r + g) * KP + kk];
                ah[mb][1] = *(const unsigned*)&Ah[(r + g + 8) * KP + kk];
                ah[mb][2] = *(const unsigned*)&Ah[(r + g) * KP + kk + 8];
                ah[mb][3] = *(const unsigned*)&Ah[(r + g + 8) * KP + kk + 8];
                al[mb][0] = *(const unsigned*)&Al[(r + g) * KP + kk];
                al[mb][1] = *(const unsigned*)&Al[(r + g + 8) * KP + kk];
                al[mb][2] = *(const unsigned*)&Al[(r + g) * KP + kk + 8];
                al[mb][3] = *(const unsigned*)&Al[(r + g + 8) * KP + kk + 8];
            }
#pragma unroll
            for (int nb = 0; nb < 8; nb++) {
                int n = warp_n + nb * 8 + g;
                unsigned bh[2], bl[2];
                bh[0] = *(const unsigned*)&Bh[n * KP + kk];
                bh[1] = *(const unsigned*)&Bh[n * KP + kk + 8];
                bl[0] = *(const unsigned*)&Bl[n * KP + kk];
                bl[1] = *(const unsigned*)&Bl[n * KP + kk + 8];
#pragma unroll
                for (int mb = 0; mb < 2; mb++) {
                    mma16816(acc[mb][nb], ah[mb], bh);
                    mma16816(acc[mb][nb], ah[mb], bl);
                    mma16816(acc[mb][nb], al[mb], bh);
                }
            }
        }
    };

    loadA(0); loadB(0);
    convStore(0);
    __syncthreads();

    for (int c = 0; c < 8; c++) {
        int buf = c & 1;
        if (c < 7) { loadA((c + 1) * 32); loadB((c + 1) * 32); }
        mmaChunk(buf);
        if (c < 7) convStore(buf ^ 1);
        __syncthreads();
    }

    // epilogue: tanh + dot with aw2, per-row reduction
    float p[2][2] = {{0.f, 0.f}, {0.f, 0.f}};
#pragma unroll
    for (int mb = 0; mb < 2; mb++) {
#pragma unroll
        for (int nb = 0; nb < 8; nb++) {
            int n0 = warp_n + nb * 8 + tg * 2;
            float w0 = __ldg(aw2 + n0), w1 = __ldg(aw2 + n0 + 1);
            float bb0 = __ldg(ab1 + n0), bb1 = __ldg(ab1 + n0 + 1);
            p[mb][0] = fmaf(tanhf(acc[mb][nb][0] + bb0), w0, p[mb][0]);
            p[mb][0] = fmaf(tanhf(acc[mb][nb][1] + bb1), w1, p[mb][0]);
            p[mb][1] = fmaf(tanhf(acc[mb][nb][2] + bb0), w0, p[mb][1]);
            p[mb][1] = fmaf(tanhf(acc[mb][nb][3] + bb1), w1, p[mb][1]);
        }
    }
#pragma unroll
    for (int mb = 0; mb < 2; mb++)
#pragma unroll
        for (int h = 0; h < 2; h++) {
            p[mb][h] += __shfl_xor_sync(0xffffffffu, p[mb][h], 1);
            p[mb][h] += __shfl_xor_sync(0xffffffffu, p[mb][h], 2);
        }
    if (tg == 0) {
#pragma unroll
        for (int mb = 0; mb < 2; mb++) {
            red[warp][mb * 16 + g] = p[mb][0];
            red[warp][mb * 16 + g + 8] = p[mb][1];
        }
    }
    __syncthreads();
    if (tid < 128) {
        int row = tid;
        int mwi = row >> 5, rl = row & 31;
        float v = red[mwi * 2][rl] + red[mwi * 2 + 1][rl] + __ldg(ab2);
        int gm = m_base + row;
        if (gm < N_NODES) g_s[gm] = v;
    }
}

// ---------------------------------------------------------------------------
// K2: one CTA per segment (batch sorted -> contiguous ranges).
// ---------------------------------------------------------------------------
__global__ __launch_bounds__(256)
void k2_pool(const float* __restrict__ x, const int* __restrict__ batch,
             const int* __restrict__ mask) {
    int seg = blockIdx.x;
    int j = threadIdx.x;

    __shared__ int sh_se[2];
    if (j < 2) {
        int target = seg + j;
        int lo = 0, hi = N_NODES;
        while (lo < hi) {
            int mid = (lo + hi) >> 1;
            if (batch[mid] < target) lo = mid + 1; else hi = mid;
        }
        sh_se[j] = lo;
    }
    __syncthreads();
    int start = sh_se[0], end = sh_se[1];

    float m = -1e30f, z = 0.f, acc = 0.f;
    float S0 = 0.f, S1 = 0.f, S2 = 0.f;
    float c0 = 0.f, c1 = 0.f, c2 = 0.f;

    float si_n = 0.f, xij_n = 0.f;
    int t1_n = 0, t2_n = 0;
    if (start < end) {
        si_n  = __ldg(g_s + start);
        t1_n  = __ldg(mask + (size_t)start * 3 + 1);
        t2_n  = __ldg(mask + (size_t)start * 3 + 2);
        xij_n = __ldg(x + (size_t)start * 256 + j);
    }

    for (int i = start; i < end; i++) {
        float si = si_n;
        int t1 = t1_n, t2 = t2_n;
        float xij = xij_n;
        int nxt = i + 1;
        if (nxt < end) {
            si_n  = __ldg(g_s + nxt);
            t1_n  = __ldg(mask + (size_t)nxt * 3 + 1);
            t2_n  = __ldg(mask + (size_t)nxt * 3 + 2);
            xij_n = __ldg(x + (size_t)nxt * 256 + j);
        }
        if (si > m) {
            float sc = __expf(m - si);
            z *= sc; acc *= sc; m = si;
        }
        float e = __expf(si - m);
        z += e;
        acc = fmaf(e, xij, acc);
        if (t1)      { S1 += xij; c1 += 1.f; }
        else if (t2) { S2 += xij; c2 += 1.f; }
        else         { S0 += xij; c0 += 1.f; }
    }

    float count = (float)(end - start);
    size_t base = (size_t)seg * 768;
    g_comb[base + j]       = (S0 + S1 + S2) / count;
    g_comb[base + 256 + j] = acc / z;
    g_S[base + j]       = S0;
    g_S[base + 256 + j] = S1;
    g_S[base + 512 + j] = S2;
    if (j == 0) {
        g_cnt[seg * 3 + 0] = c0;
        g_cnt[seg * 3 + 1] = c1;
        g_cnt[seg * 3 + 2] = c2;
    }
}

// ---------------------------------------------------------------------------
// Small GEMMs, 64x64x16 tiles, 256 threads, 4x4 microtile, register
// double-buffered global loads.
// ---------------------------------------------------------------------------
template <int EPI>
__global__ __launch_bounds__(256)
void gemm_small(const float* __restrict__ B0, const float* __restrict__ B1,
                const float* __restrict__ B2,
                const float* __restrict__ bias0, const float* __restrict__ bias1,
                const float* __restrict__ bias2, float* __restrict__ Cout) {
    constexpr int K   = (EPI == 0) ? 512 : 768;
    constexpr int lda = (EPI == 0) ? 512 : 768;
    constexpr int ldb = (EPI == 1) ? 512 : 256;
    constexpr int ldc = (EPI == 2) ? 768 : ((EPI == 1) ? 512 : 256);
    constexpr int coff = (EPI == 2) ? 512 : 0;

    const float* A = (EPI == 2) ? g_S : ((EPI == 1) ? g_comb : g_h);
    float* C = (EPI == 2) ? g_comb : ((EPI == 1) ? g_h : Cout);

    __shared__ float As[16][64];
    __shared__ float Bs[16][64];
    int tid = threadIdx.x;
    int m_base = blockIdx.y * 64;
    int n_base = blockIdx.x * 64;

    float acc[4][4];
#pragma unroll
    for (int i = 0; i < 4; i++)
#pragma unroll
        for (int j = 0; j < 4; j++) acc[i][j] = 0.f;

    int m0 = (tid >> 4) << 2;
    int j0 = (tid & 15) << 2;

    int am = tid >> 2, ac = (tid & 3) << 2;
    int bk = tid >> 4, bc = (tid & 15) << 2;

    auto brow_ptr = [&](int kk) -> const float* {
        if (EPI == 2) {
            return (kk < 256) ? (B0 + (size_t)kk * ldb)
                 : (kk < 512) ? (B1 + (size_t)(kk - 256) * ldb)
                              : (B2 + (size_t)(kk - 512) * ldb);
        }
        return B0 + (size_t)kk * ldb;
    };

    float4 pa = *(const float4*)(A + (size_t)(m_base + am) * lda + ac);
    float4 pb = *(const float4*)(brow_ptr(bk) + n_base + bc);

    for (int k0 = 0; k0 < K; k0 += 16) {
        As[ac + 0][am] = pa.x; As[ac + 1][am] = pa.y;
        As[ac + 2][am] = pa.z; As[ac + 3][am] = pa.w;
        *(float4*)&Bs[bk][bc] = pb;
        __syncthreads();

        int kn = k0 + 16;
        if (kn < K) {
            pa = *(const float4*)(A + (size_t)(m_base + am) * lda + kn + ac);
            pb = *(const float4*)(brow_ptr(kn + bk) + n_base + bc);
        }

#pragma unroll
        for (int k = 0; k < 16; k++) {
            float4 av = *(const float4*)&As[k][m0];
            float4 bv = *(const float4*)&Bs[k][j0];
            float a[4] = {av.x, av.y, av.z, av.w};
            float b[4] = {bv.x, bv.y, bv.z, bv.w};
#pragma unroll
            for (int i = 0; i < 4; i++)
#pragma unroll
                for (int jj = 0; jj < 4; jj++)
                    acc[i][jj] = fmaf(a[i], b[jj], acc[i][jj]);
        }
        __syncthreads();
    }

#pragma unroll
    for (int i = 0; i < 4; i++) {
        int m = m_base + m0 + i;
#pragma unroll
        for (int jj = 0; jj < 4; jj++) {
            int n = n_base + j0 + jj;
            float v = acc[i][jj];
            if (EPI == 0) {
                v += __ldg(bias0 + n);
            } else if (EPI == 1) {
                v += __ldg(bias0 + n);
                v = v / (1.f + __expf(-v));   // silu
            } else {
                v += g_cnt[m * 3 + 0] * __ldg(bias0 + n)
                   + g_cnt[m * 3 + 1] * __ldg(bias1 + n)
                   + g_cnt[m * 3 + 2] * __ldg(bias2 + n);
            }
            C[(size_t)m * ldc + coff + n] = v;
        }
    }
}

// ---------------------------------------------------------------------------
extern "C" void kernel_launch(void* const* d_in, const int* in_sizes, int n_in,
                              void* d_out, int out_size) {
    const float* x    = (const float*)d_in[0];
    const int*   batch = (const int*)d_in[1];
    const int*   mask  = (const int*)d_in[2];
    const float* aw1 = (const float*)d_in[4];
    const float* ab1 = (const float*)d_in[5];
    const float* aw2 = (const float*)d_in[6];
    const float* ab2 = (const float*)d_in[7];
    const float* we  = (const float*)d_in[8];
    const float* be  = (const float*)d_in[9];
    const float* wv  = (const float*)d_in[10];
    const float* bv  = (const float*)d_in[11];
    const float* wp  = (const float*)d_in[12];
    const float* bp  = (const float*)d_in[13];
    const float* w1  = (const float*)d_in[14];
    const float* b1  = (const float*)d_in[15];
    const float* w2  = (const float*)d_in[16];
    const float* b2  = (const float*)d_in[17];

    static bool attr_done = false;
    if (!attr_done) {
        cudaFuncSetAttribute(k1_scores,
                             cudaFuncAttributeMaxDynamicSharedMemorySize, 81920);
        attr_done = true;
    }

    k0_wsplit<<<128, 256>>>(aw1);
    k1_scores<<<(N_NODES + 127) / 128, 256, 81920>>>(x, ab1, aw2, ab2);
    k2_pool<<<NSEG, 256>>>(x, batch, mask);
    gemm_small<2><<<dim3(4, 16), 256>>>(we, wv, wp, be, bv, bp, nullptr);
    gemm_small<1><<<dim3(8, 16), 256>>>(w1, nullptr, nullptr, b1, nullptr, nullptr, nullptr);
    gemm_small<0><<<dim3(4, 16), 256>>>(w2, nullptr, nullptr, b2, nullptr, nullptr, (float*)d_out);
}

// round 10
// speedup vs baseline: 1.5937x; 1.0386x over previous
#include <cuda_runtime.h>
#include <cuda_fp16.h>
#include <math.h>
#include <stdint.h>

#define N_NODES 200000
#define NSEG 1024
#define KP 40   // smem k-pitch (half elems) -> conflict-free fragment LDS

// scratch (device globals: no allocation allowed)
__device__ float g_s[N_NODES];
__device__ float g_S[NSEG * 768];
__device__ float g_comb[NSEG * 768];
__device__ float g_h[NSEG * 512];
__device__ float g_cnt[NSEG * 3];
__device__ __half g_Bh[128 * 256];   // fp16(aw1), transposed [n][k]

// ---- warp mma m16n8k16 fp16 -----------------------------------------------
__device__ __forceinline__ void mma16816(float* d, const unsigned* a,
                                         const unsigned* b) {
    asm volatile(
        "mma.sync.aligned.m16n8k16.row.col.f32.f16.f16.f32 "
        "{%0,%1,%2,%3}, {%4,%5,%6,%7}, {%8,%9}, {%0,%1,%2,%3};"
        : "+f"(d[0]), "+f"(d[1]), "+f"(d[2]), "+f"(d[3])
        : "r"(a[0]), "r"(a[1]), "r"(a[2]), "r"(a[3]), "r"(b[0]), "r"(b[1]));
}

// ---------------------------------------------------------------------------
// K0: one-time fp16 quantization of aw1, transposed to [n][k].
// ---------------------------------------------------------------------------
__global__ __launch_bounds__(256)
void k0_wsplit(const float* __restrict__ aw1) {
    int idx = blockIdx.x * 256 + threadIdx.x;   // 0..32767
    int k = idx >> 7, n = idx & 127;
    g_Bh[n * 256 + k] = __float2half_rn(aw1[(size_t)k * 128 + n]);
}

// ---------------------------------------------------------------------------
// K1: s[i] = tanh(x[i]@aw1 + ab1) @ aw2 + ab2, tensor-core path.
// CTA tile 128(M) x 128(N); K in 8 chunks of 32; double-buffered smem with
// register prefetch. x split hi/lo fp16 (2-term Markidis, residual only on
// x side; weights are exact-as-quantized fp16) -> 2 MMAs per product.
// Dyn smem buffer b (half elems, stride 15360): Ah +0, Al +5120, Bh +10240.
// ---------------------------------------------------------------------------
__global__ __launch_bounds__(256)
void k1_scores(const float* __restrict__ x, const float* __restrict__ ab1,
               const float* __restrict__ aw2, const float* __restrict__ ab2) {
    extern __shared__ __align__(16) __half sm[];
    __shared__ float red[8][32];

    int tid = threadIdx.x;
    int warp = tid >> 5, lane = tid & 31;
    int g = lane >> 2, tg = lane & 3;
    int warp_m = (warp >> 1) * 32, warp_n = (warp & 1) * 64;
    int m_base = blockIdx.x * 128;

    float acc[2][8][4];
#pragma unroll
    for (int a = 0; a < 2; a++)
#pragma unroll
        for (int b = 0; b < 8; b++)
#pragma unroll
            for (int c = 0; c < 4; c++) acc[a][b][c] = 0.f;

    float4 pa[4];
    uint4 pbh[2];
    int bn = tid >> 1, bj = (tid & 1) * 2;

    auto loadA = [&](int k0) {
#pragma unroll
        for (int i = 0; i < 4; i++) {
            int idx = tid + i * 256;
            int row = idx >> 3, c4 = idx & 7;
            int gm = m_base + row;
            pa[i] = (gm < N_NODES)
                        ? *(const float4*)(x + (size_t)gm * 256 + k0 + c4 * 4)
                        : make_float4(0.f, 0.f, 0.f, 0.f);
        }
    };
    auto loadB = [&](int k0) {
#pragma unroll
        for (int j = 0; j < 2; j++)
            pbh[j] = *(const uint4*)(g_Bh + bn * 256 + k0 + (bj + j) * 8);
    };
    auto convStore = [&](int buf) {
        __half* Ah = sm + buf * 15360;
        __half* Al = Ah + 5120;
        __half* Bh = Ah + 10240;
#pragma unroll
        for (int i = 0; i < 4; i++) {
            int idx = tid + i * 256;
            int row = idx >> 3, c4 = idx & 7;
            float4 v = pa[i];
            __half2 h01 = __floats2half2_rn(v.x, v.y);
            __half2 h23 = __floats2half2_rn(v.z, v.w);
            __half2 l01 = __floats2half2_rn(v.x - __low2float(h01),
                                            v.y - __high2float(h01));
            __half2 l23 = __floats2half2_rn(v.z - __low2float(h23),
                                            v.w - __high2float(h23));
            int off = row * KP + c4 * 4;
            *(uint2*)&Ah[off] = make_uint2(*(unsigned*)&h01, *(unsigned*)&h23);
            *(uint2*)&Al[off] = make_uint2(*(unsigned*)&l01, *(unsigned*)&l23);
        }
#pragma unroll
        for (int j = 0; j < 2; j++)
            *(uint4*)&Bh[bn * KP + (bj + j) * 8] = pbh[j];
    };
    auto mmaChunk = [&](int buf) {
        const __half* Ah = sm + buf * 15360;
        const __half* Al = Ah + 5120;
        const __half* Bh = Ah + 10240;
#pragma unroll
        for (int kb = 0; kb < 2; kb++) {
            int kk = kb * 16 + tg * 2;
            unsigned ah[2][4], al[2][4];
#pragma unroll
            for (int mb = 0; mb < 2; mb++) {
                int r = warp_m + mb * 16;
                ah[mb][0] = *(const unsigned*)&Ah[(r + g) * KP + kk];
                ah[mb][1] = *(const unsigned*)&Ah[(r + g + 8) * KP + kk];
                ah[mb][2] = *(const unsigned*)&Ah[(r + g) * KP + kk + 8];
                ah[mb][3] = *(const unsigned*)&Ah[(r + g + 8) * KP + kk + 8];
                al[mb][0] = *(const unsigned*)&Al[(r + g) * KP + kk];
                al[mb][1] = *(const unsigned*)&Al[(r + g + 8) * KP + kk];
                al[mb][2] = *(const unsigned*)&Al[(r + g) * KP + kk + 8];
                al[mb][3] = *(const unsigned*)&Al[(r + g + 8) * KP + kk + 8];
            }
#pragma unroll
            for (int nb = 0; nb < 8; nb++) {
                int n = warp_n + nb * 8 + g;
                unsigned bh[2];
                bh[0] = *(const unsigned*)&Bh[n * KP + kk];
                bh[1] = *(const unsigned*)&Bh[n * KP + kk + 8];
#pragma unroll
                for (int mb = 0; mb < 2; mb++) {
                    mma16816(acc[mb][nb], ah[mb], bh);
                    mma16816(acc[mb][nb], al[mb], bh);
                }
            }
        }
    };

    loadA(0); loadB(0);
    convStore(0);
    __syncthreads();

    for (int c = 0; c < 8; c++) {
        int buf = c & 1;
        if (c < 7) { loadA((c + 1) * 32); loadB((c + 1) * 32); }
        mmaChunk(buf);
        if (c < 7) convStore(buf ^ 1);
        __syncthreads();
    }

    // epilogue: tanh + dot with aw2, per-row reduction
    float p[2][2] = {{0.f, 0.f}, {0.f, 0.f}};
#pragma unroll
    for (int mb = 0; mb < 2; mb++) {
#pragma unroll
        for (int nb = 0; nb < 8; nb++) {
            int n0 = warp_n + nb * 8 + tg * 2;
            float w0 = __ldg(aw2 + n0), w1 = __ldg(aw2 + n0 + 1);
            float bb0 = __ldg(ab1 + n0), bb1 = __ldg(ab1 + n0 + 1);
            p[mb][0] = fmaf(tanhf(acc[mb][nb][0] + bb0), w0, p[mb][0]);
            p[mb][0] = fmaf(tanhf(acc[mb][nb][1] + bb1), w1, p[mb][0]);
            p[mb][1] = fmaf(tanhf(acc[mb][nb][2] + bb0), w0, p[mb][1]);
            p[mb][1] = fmaf(tanhf(acc[mb][nb][3] + bb1), w1, p[mb][1]);
        }
    }
#pragma unroll
    for (int mb = 0; mb < 2; mb++)
#pragma unroll
        for (int h = 0; h < 2; h++) {
            p[mb][h] += __shfl_xor_sync(0xffffffffu, p[mb][h], 1);
            p[mb][h] += __shfl_xor_sync(0xffffffffu, p[mb][h], 2);
        }
    if (tg == 0) {
#pragma unroll
        for (int mb = 0; mb < 2; mb++) {
            red[warp][mb * 16 + g] = p[mb][0];
            red[warp][mb * 16 + g + 8] = p[mb][1];
        }
    }
    __syncthreads();
    if (tid < 128) {
        int row = tid;
        int mwi = row >> 5, rl = row & 31;
        float v = red[mwi * 2][rl] + red[mwi * 2 + 1][rl] + __ldg(ab2);
        int gm = m_base + row;
        if (gm < N_NODES) g_s[gm] = v;
    }
}

// ---------------------------------------------------------------------------
// K2: one CTA per segment (batch sorted -> contiguous ranges).
// ---------------------------------------------------------------------------
__global__ __launch_bounds__(256)
void k2_pool(const float* __restrict__ x, const int* __restrict__ batch,
             const int* __restrict__ mask) {
    int seg = blockIdx.x;
    int j = threadIdx.x;

    __shared__ int sh_se[2];
    if (j < 2) {
        int target = seg + j;
        int lo = 0, hi = N_NODES;
        while (lo < hi) {
            int mid = (lo + hi) >> 1;
            if (batch[mid] < target) lo = mid + 1; else hi = mid;
        }
        sh_se[j] = lo;
    }
    __syncthreads();
    int start = sh_se[0], end = sh_se[1];

    float m = -1e30f, z = 0.f, acc = 0.f;
    float S0 = 0.f, S1 = 0.f, S2 = 0.f;
    float c0 = 0.f, c1 = 0.f, c2 = 0.f;

    float si_n = 0.f, xij_n = 0.f;
    int t1_n = 0, t2_n = 0;
    if (start < end) {
        si_n  = __ldg(g_s + start);
        t1_n  = __ldg(mask + (size_t)start * 3 + 1);
        t2_n  = __ldg(mask + (size_t)start * 3 + 2);
        xij_n = __ldg(x + (size_t)start * 256 + j);
    }

    for (int i = start; i < end; i++) {
        float si = si_n;
        int t1 = t1_n, t2 = t2_n;
        float xij = xij_n;
        int nxt = i + 1;
        if (nxt < end) {
            si_n  = __ldg(g_s + nxt);
            t1_n  = __ldg(mask + (size_t)nxt * 3 + 1);
            t2_n  = __ldg(mask + (size_t)nxt * 3 + 2);
            xij_n = __ldg(x + (size_t)nxt * 256 + j);
        }
        if (si > m) {
            float sc = __expf(m - si);
            z *= sc; acc *= sc; m = si;
        }
        float e = __expf(si - m);
        z += e;
        acc = fmaf(e, xij, acc);
        if (t1)      { S1 += xij; c1 += 1.f; }
        else if (t2) { S2 += xij; c2 += 1.f; }
        else         { S0 += xij; c0 += 1.f; }
    }

    float count = (float)(end - start);
    size_t base = (size_t)seg * 768;
    g_comb[base + j]       = (S0 + S1 + S2) / count;
    g_comb[base + 256 + j] = acc / z;
    g_S[base + j]       = S0;
    g_S[base + 256 + j] = S1;
    g_S[base + 512 + j] = S2;
    if (j == 0) {
        g_cnt[seg * 3 + 0] = c0;
        g_cnt[seg * 3 + 1] = c1;
        g_cnt[seg * 3 + 2] = c2;
    }
}

// ---------------------------------------------------------------------------
// Small GEMMs, 64(M)x32(N)x16 tiles (doubled grid vs 64x64 for occupancy),
// 256 threads, 2x4 microtile, register double-buffered global loads.
// EPI==2: phys_pool = [S0 S1 S2] @ [we;wv;wp] + c_t*b_t  -> g_comb[:,512:]
// EPI==1: h = silu(g_comb @ w1 + b1)                      -> g_h
// EPI==0: out = g_h @ w2 + b2                             -> d_out
// ---------------------------------------------------------------------------
template <int EPI>
__global__ __launch_bounds__(256)
void gemm_small(const float* __restrict__ B0, const float* __restrict__ B1,
                const float* __restrict__ B2,
                const float* __restrict__ bias0, const float* __restrict__ bias1,
                const float* __restrict__ bias2, float* __restrict__ Cout) {
    constexpr int K   = (EPI == 0) ? 512 : 768;
    constexpr int lda = (EPI == 0) ? 512 : 768;
    constexpr int ldb = (EPI == 1) ? 512 : 256;
    constexpr int ldc = (EPI == 2) ? 768 : ((EPI == 1) ? 512 : 256);
    constexpr int coff = (EPI == 2) ? 512 : 0;

    const float* A = (EPI == 2) ? g_S : ((EPI == 1) ? g_comb : g_h);
    float* C = (EPI == 2) ? g_comb : ((EPI == 1) ? g_h : Cout);

    __shared__ float As[16][64];
    __shared__ float Bs[16][32];
    int tid = threadIdx.x;
    int m_base = blockIdx.y * 64;
    int n_base = blockIdx.x * 32;

    float acc[2][4];
#pragma unroll
    for (int i = 0; i < 2; i++)
#pragma unroll
        for (int j = 0; j < 4; j++) acc[i][j] = 0.f;

    int m0 = (tid >> 3) << 1;        // 0,2,..,62
    int j0 = (tid & 7) << 2;         // 0,4,..,28

    int am = tid >> 2, ac = (tid & 3) << 2;            // A: 256 float4
    int bk = tid >> 3, bc = (tid & 7) << 2;            // B: first 128 threads

    auto brow_ptr = [&](int kk) -> const float* {
        if (EPI == 2) {
            return (kk < 256) ? (B0 + (size_t)kk * ldb)
                 : (kk < 512) ? (B1 + (size_t)(kk - 256) * ldb)
                              : (B2 + (size_t)(kk - 512) * ldb);
        }
        return B0 + (size_t)kk * ldb;
    };

    float4 pa = *(const float4*)(A + (size_t)(m_base + am) * lda + ac);
    float4 pb = make_float4(0.f, 0.f, 0.f, 0.f);
    if (tid < 128) pb = *(const float4*)(brow_ptr(bk) + n_base + bc);

    for (int k0 = 0; k0 < K; k0 += 16) {
        As[ac + 0][am] = pa.x; As[ac + 1][am] = pa.y;
        As[ac + 2][am] = pa.z; As[ac + 3][am] = pa.w;
        if (tid < 128) *(float4*)&Bs[bk][bc] = pb;
        __syncthreads();

        int kn = k0 + 16;
        if (kn < K) {
            pa = *(const float4*)(A + (size_t)(m_base + am) * lda + kn + ac);
            if (tid < 128) pb = *(const float4*)(brow_ptr(kn + bk) + n_base + bc);
        }

#pragma unroll
        for (int k = 0; k < 16; k++) {
            float a0 = As[k][m0], a1 = As[k][m0 + 1];
            float4 bv = *(const float4*)&Bs[k][j0];
            float b[4] = {bv.x, bv.y, bv.z, bv.w};
#pragma unroll
            for (int jj = 0; jj < 4; jj++) {
                acc[0][jj] = fmaf(a0, b[jj], acc[0][jj]);
                acc[1][jj] = fmaf(a1, b[jj], acc[1][jj]);
            }
        }
        __syncthreads();
    }

#pragma unroll
    for (int i = 0; i < 2; i++) {
        int m = m_base + m0 + i;
#pragma unroll
        for (int jj = 0; jj < 4; jj++) {
            int n = n_base + j0 + jj;
            float v = acc[i][jj];
            if (EPI == 0) {
                v += __ldg(bias0 + n);
            } else if (EPI == 1) {
                v += __ldg(bias0 + n);
                v = v / (1.f + __expf(-v));   // silu
            } else {
                v += g_cnt[m * 3 + 0] * __ldg(bias0 + n)
                   + g_cnt[m * 3 + 1] * __ldg(bias1 + n)
                   + g_cnt[m * 3 + 2] * __ldg(bias2 + n);
            }
            C[(size_t)m * ldc + coff + n] = v;
        }
    }
}

// ---------------------------------------------------------------------------
extern "C" void kernel_launch(void* const* d_in, const int* in_sizes, int n_in,
                              void* d_out, int out_size) {
    const float* x    = (const float*)d_in[0];
    const int*   batch = (const int*)d_in[1];
    const int*   mask  = (const int*)d_in[2];
    const float* aw1 = (const float*)d_in[4];
    const float* ab1 = (const float*)d_in[5];
    const float* aw2 = (const float*)d_in[6];
    const float* ab2 = (const float*)d_in[7];
    const float* we  = (const float*)d_in[8];
    const float* be  = (const float*)d_in[9];
    const float* wv  = (const float*)d_in[10];
    const float* bv  = (const float*)d_in[11];
    const float* wp  = (const float*)d_in[12];
    const float* bp  = (const float*)d_in[13];
    const float* w1  = (const float*)d_in[14];
    const float* b1  = (const float*)d_in[15];
    const float* w2  = (const float*)d_in[16];
    const float* b2  = (const float*)d_in[17];

    static bool attr_done = false;
    if (!attr_done) {
        cudaFuncSetAttribute(k1_scores,
                             cudaFuncAttributeMaxDynamicSharedMemorySize, 61440);
        attr_done = true;
    }

    k0_wsplit<<<128, 256>>>(aw1);
    k1_scores<<<(N_NODES + 127) / 128, 256, 61440>>>(x, ab1, aw2, ab2);
    k2_pool<<<NSEG, 256>>>(x, batch, mask);
    gemm_small<2><<<dim3(8, 16), 256>>>(we, wv, wp, be, bv, bp, nullptr);
    gemm_small<1><<<dim3(16, 16), 256>>>(w1, nullptr, nullptr, b1, nullptr, nullptr, nullptr);
    gemm_small<0><<<dim3(8, 16), 256>>>(w2, nullptr, nullptr, b2, nullptr, nullptr, (float*)d_out);
}

// round 11
// speedup vs baseline: 1.7383x; 1.0907x over previous
#include <cuda_runtime.h>
#include <cuda_fp16.h>
#include <math.h>
#include <stdint.h>

#define N_NODES 200000
#define NSEG 1024
#define KP 40   // smem k-pitch (half elems) -> conflict-free ldmatrix phases

// scratch (device globals: no allocation allowed)
__device__ float g_s[N_NODES];
__device__ float g_S[NSEG * 768];
__device__ float g_comb[NSEG * 768];
__device__ float g_h[NSEG * 512];
__device__ float g_cnt[NSEG * 3];
// fp16(aw1) in 8 chunk-tiles, each [n=128][kin=32] with pitch KP (5120 halves)
__device__ __half g_Bh[8 * 5120];

__device__ __forceinline__ uint32_t smem_u32(const void* p) {
    uint32_t a;
    asm("{ .reg .u64 t; cvta.to.shared.u64 t, %1; cvt.u32.u64 %0, t; }"
        : "=r"(a) : "l"(p));
    return a;
}
__device__ __forceinline__ void mma16816(float* d, const unsigned* a,
                                         const unsigned* b) {
    asm volatile(
        "mma.sync.aligned.m16n8k16.row.col.f32.f16.f16.f32 "
        "{%0,%1,%2,%3}, {%4,%5,%6,%7}, {%8,%9}, {%0,%1,%2,%3};"
        : "+f"(d[0]), "+f"(d[1]), "+f"(d[2]), "+f"(d[3])
        : "r"(a[0]), "r"(a[1]), "r"(a[2]), "r"(a[3]), "r"(b[0]), "r"(b[1]));
}
__device__ __forceinline__ void ldsm4(unsigned* r, uint32_t addr) {
    asm volatile(
        "ldmatrix.sync.aligned.m8n8.x4.shared.b16 {%0,%1,%2,%3}, [%4];"
        : "=r"(r[0]), "=r"(r[1]), "=r"(r[2]), "=r"(r[3]) : "r"(addr));
}

// ---------------------------------------------------------------------------
// K0: one-time fp16 quantization of aw1 into chunk-tiled [n][kin] images.
// ---------------------------------------------------------------------------
__global__ __launch_bounds__(256)
void k0_wsplit(const float* __restrict__ aw1) {
    int idx = blockIdx.x * 256 + threadIdx.x;   // 0..32767
    int k = idx >> 7, n = idx & 127;
    int chunk = k >> 5, kin = k & 31;
    g_Bh[chunk * 5120 + n * KP + kin] = __float2half_rn(aw1[(size_t)k * 128 + n]);
}

// ---------------------------------------------------------------------------
// K1: s[i] = tanh(x[i]@aw1 + ab1) @ aw2 + ab2, tensor-core path.
// CTA tile 128(M) x 128(N); K in 8 chunks of 32. Pure fp16 (x quantized).
// B resident in smem (all 8 chunks, 80KB, loaded once). A double-buffered
// with register prefetch; fragments via ldmatrix.x4.
// Dyn smem (bytes): Abuf0 [0,10240), Abuf1 [10240,20480), B [20480,102400).
// ---------------------------------------------------------------------------
__global__ __launch_bounds__(256)
void k1_scores(const float* __restrict__ x, const float* __restrict__ ab1,
               const float* __restrict__ aw2, const float* __restrict__ ab2) {
    extern __shared__ __align__(16) __half sm[];
    __shared__ float red[8][32];

    int tid = threadIdx.x;
    int warp = tid >> 5, lane = tid & 31;
    int g = lane >> 2, tg = lane & 3;
    int warp_m = (warp >> 1) * 32, warp_n = (warp & 1) * 64;
    int m_base = blockIdx.x * 128;
    uint32_t sb = smem_u32(sm);

    // ldmatrix lane address components
    int arow = lane & 15, akoff = (lane >> 4) * 8;
    int bnrow = ((lane >> 4) << 3) + (lane & 7), bkoff = ((lane >> 3) & 1) * 8;

    float acc[2][8][4];
#pragma unroll
    for (int a = 0; a < 2; a++)
#pragma unroll
        for (int b = 0; b < 8; b++)
#pragma unroll
            for (int c = 0; c < 4; c++) acc[a][b][c] = 0.f;

    // resident B: copy all 8 chunk-tiles (5120 uint4)
    {
        const uint4* src = (const uint4*)g_Bh;
        uint4* dst = (uint4*)(sm + 10240);   // +20480 bytes
#pragma unroll
        for (int i = 0; i < 20; i++) dst[tid + i * 256] = src[tid + i * 256];
    }

    float4 pa[4];
    auto loadA = [&](int k0) {
#pragma unroll
        for (int i = 0; i < 4; i++) {
            int idx = tid + i * 256;
            int row = idx >> 3, c4 = idx & 7;
            int gm = m_base + row;
            pa[i] = (gm < N_NODES)
                        ? *(const float4*)(x + (size_t)gm * 256 + k0 + c4 * 4)
                        : make_float4(0.f, 0.f, 0.f, 0.f);
        }
    };
    auto convStore = [&](int buf) {
        __half* Ah = sm + buf * 5120;
#pragma unroll
        for (int i = 0; i < 4; i++) {
            int idx = tid + i * 256;
            int row = idx >> 3, c4 = idx & 7;
            float4 v = pa[i];
            __half2 h01 = __floats2half2_rn(v.x, v.y);
            __half2 h23 = __floats2half2_rn(v.z, v.w);
            *(uint2*)&Ah[row * KP + c4 * 4] =
                make_uint2(*(unsigned*)&h01, *(unsigned*)&h23);
        }
    };
    auto mmaChunk = [&](int c, int buf) {
        uint32_t aB = sb + buf * 10240;
        uint32_t bB = sb + 20480 + c * 10240;
#pragma unroll
        for (int kb = 0; kb < 2; kb++) {
            unsigned ah[2][4];
            ldsm4(ah[0], aB + ((warp_m + arow) * KP + kb * 16 + akoff) * 2);
            ldsm4(ah[1], aB + ((warp_m + 16 + arow) * KP + kb * 16 + akoff) * 2);
#pragma unroll
            for (int nbp = 0; nbp < 4; nbp++) {
                unsigned bb[4];
                ldsm4(bb, bB + ((warp_n + nbp * 16 + bnrow) * KP + kb * 16 + bkoff) * 2);
#pragma unroll
                for (int mb = 0; mb < 2; mb++) {
                    mma16816(acc[mb][nbp * 2 + 0], ah[mb], bb + 0);
                    mma16816(acc[mb][nbp * 2 + 1], ah[mb], bb + 2);
                }
            }
        }
    };

    loadA(0);
    convStore(0);
    __syncthreads();

    for (int c = 0; c < 8; c++) {
        int buf = c & 1;
        if (c < 7) loadA((c + 1) * 32);
        mmaChunk(c, buf);
        if (c < 7) convStore(buf ^ 1);
        __syncthreads();
    }

    // epilogue: tanh + dot with aw2, per-row reduction
    float p[2][2] = {{0.f, 0.f}, {0.f, 0.f}};
#pragma unroll
    for (int mb = 0; mb < 2; mb++) {
#pragma unroll
        for (int nb = 0; nb < 8; nb++) {
            int n0 = warp_n + nb * 8 + tg * 2;
            float w0 = __ldg(aw2 + n0), w1 = __ldg(aw2 + n0 + 1);
            float bb0 = __ldg(ab1 + n0), bb1 = __ldg(ab1 + n0 + 1);
            p[mb][0] = fmaf(tanhf(acc[mb][nb][0] + bb0), w0, p[mb][0]);
            p[mb][0] = fmaf(tanhf(acc[mb][nb][1] + bb1), w1, p[mb][0]);
            p[mb][1] = fmaf(tanhf(acc[mb][nb][2] + bb0), w0, p[mb][1]);
            p[mb][1] = fmaf(tanhf(acc[mb][nb][3] + bb1), w1, p[mb][1]);
        }
    }
#pragma unroll
    for (int mb = 0; mb < 2; mb++)
#pragma unroll
        for (int h = 0; h < 2; h++) {
            p[mb][h] += __shfl_xor_sync(0xffffffffu, p[mb][h], 1);
            p[mb][h] += __shfl_xor_sync(0xffffffffu, p[mb][h], 2);
        }
    if (tg == 0) {
#pragma unroll
        for (int mb = 0; mb < 2; mb++) {
            red[warp][mb * 16 + g] = p[mb][0];
            red[warp][mb * 16 + g + 8] = p[mb][1];
        }
    }
    __syncthreads();
    if (tid < 128) {
        int row = tid;
        int mwi = row >> 5, rl = row & 31;
        float v = red[mwi * 2][rl] + red[mwi * 2 + 1][rl] + __ldg(ab2);
        int gm = m_base + row;
        if (gm < N_NODES) g_s[gm] = v;
    }
}

// ---------------------------------------------------------------------------
// K2: one CTA per segment (batch sorted -> contiguous ranges).
// ---------------------------------------------------------------------------
__global__ __launch_bounds__(256)
void k2_pool(const float* __restrict__ x, const int* __restrict__ batch,
             const int* __restrict__ mask) {
    int seg = blockIdx.x;
    int j = threadIdx.x;

    __shared__ int sh_se[2];
    if (j < 2) {
        int target = seg + j;
        int lo = 0, hi = N_NODES;
        while (lo < hi) {
            int mid = (lo + hi) >> 1;
            if (batch[mid] < target) lo = mid + 1; else hi = mid;
        }
        sh_se[j] = lo;
    }
    __syncthreads();
    int start = sh_se[0], end = sh_se[1];

    float m = -1e30f, z = 0.f, acc = 0.f;
    float S0 = 0.f, S1 = 0.f, S2 = 0.f;
    float c0 = 0.f, c1 = 0.f, c2 = 0.f;

    float si_n = 0.f, xij_n = 0.f;
    int t1_n = 0, t2_n = 0;
    if (start < end) {
        si_n  = __ldg(g_s + start);
        t1_n  = __ldg(mask + (size_t)start * 3 + 1);
        t2_n  = __ldg(mask + (size_t)start * 3 + 2);
        xij_n = __ldg(x + (size_t)start * 256 + j);
    }

    for (int i = start; i < end; i++) {
        float si = si_n;
        int t1 = t1_n, t2 = t2_n;
        float xij = xij_n;
        int nxt = i + 1;
        if (nxt < end) {
            si_n  = __ldg(g_s + nxt);
            t1_n  = __ldg(mask + (size_t)nxt * 3 + 1);
            t2_n  = __ldg(mask + (size_t)nxt * 3 + 2);
            xij_n = __ldg(x + (size_t)nxt * 256 + j);
        }
        if (si > m) {
            float sc = __expf(m - si);
            z *= sc; acc *= sc; m = si;
        }
        float e = __expf(si - m);
        z += e;
        acc = fmaf(e, xij, acc);
        if (t1)      { S1 += xij; c1 += 1.f; }
        else if (t2) { S2 += xij; c2 += 1.f; }
        else         { S0 += xij; c0 += 1.f; }
    }

    float count = (float)(end - start);
    size_t base = (size_t)seg * 768;
    g_comb[base + j]       = (S0 + S1 + S2) / count;
    g_comb[base + 256 + j] = acc / z;
    g_S[base + j]       = S0;
    g_S[base + 256 + j] = S1;
    g_S[base + 512 + j] = S2;
    if (j == 0) {
        g_cnt[seg * 3 + 0] = c0;
        g_cnt[seg * 3 + 1] = c1;
        g_cnt[seg * 3 + 2] = c2;
    }
}

// ---------------------------------------------------------------------------
// Small GEMMs, 64(M)x32(N)x16 tiles, 256 threads, 2x4 microtile, register
// double-buffered global loads.
// ---------------------------------------------------------------------------
template <int EPI>
__global__ __launch_bounds__(256)
void gemm_small(const float* __restrict__ B0, const float* __restrict__ B1,
                const float* __restrict__ B2,
                const float* __restrict__ bias0, const float* __restrict__ bias1,
                const float* __restrict__ bias2, float* __restrict__ Cout) {
    constexpr int K   = (EPI == 0) ? 512 : 768;
    constexpr int lda = (EPI == 0) ? 512 : 768;
    constexpr int ldb = (EPI == 1) ? 512 : 256;
    constexpr int ldc = (EPI == 2) ? 768 : ((EPI == 1) ? 512 : 256);
    constexpr int coff = (EPI == 2) ? 512 : 0;

    const float* A = (EPI == 2) ? g_S : ((EPI == 1) ? g_comb : g_h);
    float* C = (EPI == 2) ? g_comb : ((EPI == 1) ? g_h : Cout);

    __shared__ float As[16][64];
    __shared__ float Bs[16][32];
    int tid = threadIdx.x;
    int m_base = blockIdx.y * 64;
    int n_base = blockIdx.x * 32;

    float acc[2][4];
#pragma unroll
    for (int i = 0; i < 2; i++)
#pragma unroll
        for (int j = 0; j < 4; j++) acc[i][j] = 0.f;

    int m0 = (tid >> 3) << 1;
    int j0 = (tid & 7) << 2;

    int am = tid >> 2, ac = (tid & 3) << 2;
    int bk = tid >> 3, bc = (tid & 7) << 2;

    auto brow_ptr = [&](int kk) -> const float* {
        if (EPI == 2) {
            return (kk < 256) ? (B0 + (size_t)kk * ldb)
                 : (kk < 512) ? (B1 + (size_t)(kk - 256) * ldb)
                              : (B2 + (size_t)(kk - 512) * ldb);
        }
        return B0 + (size_t)kk * ldb;
    };

    float4 pa = *(const float4*)(A + (size_t)(m_base + am) * lda + ac);
    float4 pb = make_float4(0.f, 0.f, 0.f, 0.f);
    if (tid < 128) pb = *(const float4*)(brow_ptr(bk) + n_base + bc);

    for (int k0 = 0; k0 < K; k0 += 16) {
        As[ac + 0][am] = pa.x; As[ac + 1][am] = pa.y;
        As[ac + 2][am] = pa.z; As[ac + 3][am] = pa.w;
        if (tid < 128) *(float4*)&Bs[bk][bc] = pb;
        __syncthreads();

        int kn = k0 + 16;
        if (kn < K) {
            pa = *(const float4*)(A + (size_t)(m_base + am) * lda + kn + ac);
            if (tid < 128) pb = *(const float4*)(brow_ptr(kn + bk) + n_base + bc);
        }

#pragma unroll
        for (int k = 0; k < 16; k++) {
            float a0 = As[k][m0], a1 = As[k][m0 + 1];
            float4 bv = *(const float4*)&Bs[k][j0];
            float b[4] = {bv.x, bv.y, bv.z, bv.w};
#pragma unroll
            for (int jj = 0; jj < 4; jj++) {
                acc[0][jj] = fmaf(a0, b[jj], acc[0][jj]);
                acc[1][jj] = fmaf(a1, b[jj], acc[1][jj]);
            }
        }
        __syncthreads();
    }

#pragma unroll
    for (int i = 0; i < 2; i++) {
        int m = m_base + m0 + i;
#pragma unroll
        for (int jj = 0; jj < 4; jj++) {
            int n = n_base + j0 + jj;
            float v = acc[i][jj];
            if (EPI == 0) {
                v += __ldg(bias0 + n);
            } else if (EPI == 1) {
                v += __ldg(bias0 + n);
                v = v / (1.f + __expf(-v));   // silu
            } else {
                v += g_cnt[m * 3 + 0] * __ldg(bias0 + n)
                   + g_cnt[m * 3 + 1] * __ldg(bias1 + n)
                   + g_cnt[m * 3 + 2] * __ldg(bias2 + n);
            }
            C[(size_t)m * ldc + coff + n] = v;
        }
    }
}

// ---------------------------------------------------------------------------
extern "C" void kernel_launch(void* const* d_in, const int* in_sizes, int n_in,
                              void* d_out, int out_size) {
    const float* x    = (const float*)d_in[0];
    const int*   batch = (const int*)d_in[1];
    const int*   mask  = (const int*)d_in[2];
    const float* aw1 = (const float*)d_in[4];
    const float* ab1 = (const float*)d_in[5];
    const float* aw2 = (const float*)d_in[6];
    const float* ab2 = (const float*)d_in[7];
    const float* we  = (const float*)d_in[8];
    const float* be  = (const float*)d_in[9];
    const float* wv  = (const float*)d_in[10];
    const float* bv  = (const float*)d_in[11];
    const float* wp  = (const float*)d_in[12];
    const float* bp  = (const float*)d_in[13];
    const float* w1  = (const float*)d_in[14];
    const float* b1  = (const float*)d_in[15];
    const float* w2  = (const float*)d_in[16];
    const float* b2  = (const float*)d_in[17];

    static bool attr_done = false;
    if (!attr_done) {
        cudaFuncSetAttribute(k1_scores,
                             cudaFuncAttributeMaxDynamicSharedMemorySize, 102400);
        attr_done = true;
    }

    k0_wsplit<<<128, 256>>>(aw1);
    k1_scores<<<(N_NODES + 127) / 128, 256, 102400>>>(x, ab1, aw2, ab2);
    k2_pool<<<NSEG, 256>>>(x, batch, mask);
    gemm_small<2><<<dim3(8, 16), 256>>>(we, wv, wp, be, bv, bp, nullptr);
    gemm_small<1><<<dim3(16, 16), 256>>>(w1, nullptr, nullptr, b1, nullptr, nullptr, nullptr);
    gemm_small<0><<<dim3(8, 16), 256>>>(w2, nullptr, nullptr, b2, nullptr, nullptr, (float*)d_out);
}

// round 12
// speedup vs baseline: 1.9385x; 1.1152x over previous
#include <cuda_runtime.h>
#include <cuda_fp16.h>
#include <math.h>
#include <stdint.h>

#define N_NODES 200000
#define NSEG 1024
#define KP 40   // smem k-pitch (half elems): 80B rows -> conflict-free ldmatrix

// scratch (device globals: no allocation allowed)
__device__ float g_s[N_NODES];
__device__ float g_S[NSEG * 768];
__device__ float g_comb[NSEG * 768];
__device__ float g_h[NSEG * 512];
__device__ float g_cnt[NSEG * 3];
__device__ __half g_Bh[8 * 5120];          // fp16(aw1), 8 chunk-tiles [n][kin] pitch KP
__device__ __half g_xh[(size_t)N_NODES * 256];  // fp16(x)

__device__ __forceinline__ uint32_t smem_u32(const void* p) {
    uint32_t a;
    asm("{ .reg .u64 t; cvta.to.shared.u64 t, %1; cvt.u32.u64 %0, t; }"
        : "=r"(a) : "l"(p));
    return a;
}
__device__ __forceinline__ void mma16816(float* d, const unsigned* a,
                                         const unsigned* b) {
    asm volatile(
        "mma.sync.aligned.m16n8k16.row.col.f32.f16.f16.f32 "
        "{%0,%1,%2,%3}, {%4,%5,%6,%7}, {%8,%9}, {%0,%1,%2,%3};"
        : "+f"(d[0]), "+f"(d[1]), "+f"(d[2]), "+f"(d[3])
        : "r"(a[0]), "r"(a[1]), "r"(a[2]), "r"(a[3]), "r"(b[0]), "r"(b[1]));
}
__device__ __forceinline__ void ldsm4(unsigned* r, uint32_t addr) {
    asm volatile(
        "ldmatrix.sync.aligned.m8n8.x4.shared.b16 {%0,%1,%2,%3}, [%4];"
        : "=r"(r[0]), "=r"(r[1]), "=r"(r[2]), "=r"(r[3]) : "r"(addr));
}
#define CP_COMMIT() asm volatile("cp.async.commit_group;" ::: "memory")

// ---------------------------------------------------------------------------
// K0: one-time fp16 quantization of aw1 into chunk-tiled [n][kin] images.
// ---------------------------------------------------------------------------
__global__ __launch_bounds__(256)
void k0_wsplit(const float* __restrict__ aw1) {
    int idx = blockIdx.x * 256 + threadIdx.x;   // 0..32767
    int k = idx >> 7, n = idx & 127;
    int chunk = k >> 5, kin = k & 31;
    g_Bh[chunk * 5120 + n * KP + kin] = __float2half_rn(aw1[(size_t)k * 128 + n]);
}

// ---------------------------------------------------------------------------
// KC: x (fp32) -> g_xh (fp16), pure bandwidth kernel, 8 elems/thread.
// ---------------------------------------------------------------------------
__global__ __launch_bounds__(256)
void k_convert(const float* __restrict__ x) {
    size_t i = ((size_t)blockIdx.x * 256 + threadIdx.x) * 8;   // grid covers exactly
    float4 a = *(const float4*)(x + i);
    float4 b = *(const float4*)(x + i + 4);
    __half2 h0 = __floats2half2_rn(a.x, a.y);
    __half2 h1 = __floats2half2_rn(a.z, a.w);
    __half2 h2 = __floats2half2_rn(b.x, b.y);
    __half2 h3 = __floats2half2_rn(b.z, b.w);
    *(uint4*)(g_xh + i) = make_uint4(*(unsigned*)&h0, *(unsigned*)&h1,
                                     *(unsigned*)&h2, *(unsigned*)&h3);
}

// ---------------------------------------------------------------------------
// K1: s[i] = tanh(x[i]@aw1 + ab1) @ aw2 + ab2, tensor-core path.
// A (fp16 x) streamed via cp.async 3-stage ring (8KB data/stage, pitch KP);
// B resident in smem (80KB, copied once, L2-hot). One bar per chunk.
// Dyn smem (bytes): stages [0,30720), B [30720,112640).
// ---------------------------------------------------------------------------
__global__ __launch_bounds__(256)
void k1_scores(const float* __restrict__ ab1, const float* __restrict__ aw2,
               const float* __restrict__ ab2) {
    extern __shared__ __align__(16) char smc[];
    __shared__ float red[8][32];

    int tid = threadIdx.x;
    int warp = tid >> 5, lane = tid & 31;
    int g = lane >> 2, tg = lane & 3;
    int warp_m = (warp >> 1) * 32, warp_n = (warp & 1) * 64;
    int m_base = blockIdx.x * 128;
    uint32_t sb = smem_u32(smc);

    // ldmatrix lane address components
    int arow = lane & 15, akoff = (lane >> 4) * 8;
    int bnrow = ((lane >> 4) << 3) + (lane & 7), bkoff = ((lane >> 3) & 1) * 8;

    float acc[2][8][4];
#pragma unroll
    for (int a = 0; a < 2; a++)
#pragma unroll
        for (int b = 0; b < 8; b++)
#pragma unroll
            for (int c = 0; c < 4; c++) acc[a][b][c] = 0.f;

    // resident B: 81920B = 5120 uint4 (source is 80KB total -> L2-resident)
    {
        const uint4* src = (const uint4*)g_Bh;
        uint4* dst = (uint4*)(smc + 30720);
#pragma unroll
        for (int i = 0; i < 20; i++) dst[tid + i * 256] = src[tid + i * 256];
    }

    // cp.async one A chunk (128 rows x 32 k fp16) into stage s
    auto copyA = [&](int c, int s) {
        uint32_t stage = sb + s * 10240;
#pragma unroll
        for (int i = 0; i < 2; i++) {
            int o = tid + i * 256;            // 0..511
            int row = o >> 2, q = o & 3;
            int gm = m_base + row;
            const __half* src = g_xh + (size_t)gm * 256 + c * 32 + q * 8;
            uint32_t dst = stage + row * 80 + q * 16;
            int sz = (gm < N_NODES) ? 16 : 0;
            asm volatile("cp.async.cg.shared.global [%0], [%1], 16, %2;"
                         :: "r"(dst), "l"(src), "r"(sz) : "memory");
        }
        CP_COMMIT();
    };

    auto mmaChunk = [&](int c, int s) {
        uint32_t aB = sb + s * 10240;
        uint32_t bB = sb + 30720 + c * 10240;
#pragma unroll
        for (int kb = 0; kb < 2; kb++) {
            unsigned ah[2][4];
            ldsm4(ah[0], aB + (warp_m + arow) * 80 + (kb * 16 + akoff) * 2);
            ldsm4(ah[1], aB + (warp_m + 16 + arow) * 80 + (kb * 16 + akoff) * 2);
#pragma unroll
            for (int nbp = 0; nbp < 4; nbp++) {
                unsigned bb[4];
                ldsm4(bb, bB + (warp_n + nbp * 16 + bnrow) * 80 + (kb * 16 + bkoff) * 2);
#pragma unroll
                for (int mb = 0; mb < 2; mb++) {
                    mma16816(acc[mb][nbp * 2 + 0], ah[mb], bb + 0);
                    mma16816(acc[mb][nbp * 2 + 1], ah[mb], bb + 2);
                }
            }
        }
    };

    copyA(0, 0);
    copyA(1, 1);

#pragma unroll
    for (int c = 0; c < 8; c++) {
        if (c < 7) {
            asm volatile("cp.async.wait_group 1;" ::: "memory");
        } else {
            asm volatile("cp.async.wait_group 0;" ::: "memory");
        }
        __syncthreads();     // chunk c resident in all lanes; prior stage free
        if (c < 6) copyA(c + 2, (c + 2) % 3);
        mmaChunk(c, c % 3);
    }

    // epilogue: tanh + dot with aw2, per-row reduction
    float p[2][2] = {{0.f, 0.f}, {0.f, 0.f}};
#pragma unroll
    for (int mb = 0; mb < 2; mb++) {
#pragma unroll
        for (int nb = 0; nb < 8; nb++) {
            int n0 = warp_n + nb * 8 + tg * 2;
            float w0 = __ldg(aw2 + n0), w1 = __ldg(aw2 + n0 + 1);
            float bb0 = __ldg(ab1 + n0), bb1 = __ldg(ab1 + n0 + 1);
            p[mb][0] = fmaf(tanhf(acc[mb][nb][0] + bb0), w0, p[mb][0]);
            p[mb][0] = fmaf(tanhf(acc[mb][nb][1] + bb1), w1, p[mb][0]);
            p[mb][1] = fmaf(tanhf(acc[mb][nb][2] + bb0), w0, p[mb][1]);
            p[mb][1] = fmaf(tanhf(acc[mb][nb][3] + bb1), w1, p[mb][1]);
        }
    }
#pragma unroll
    for (int mb = 0; mb < 2; mb++)
#pragma unroll
        for (int h = 0; h < 2; h++) {
            p[mb][h] += __shfl_xor_sync(0xffffffffu, p[mb][h], 1);
            p[mb][h] += __shfl_xor_sync(0xffffffffu, p[mb][h], 2);
        }
    if (tg == 0) {
#pragma unroll
        for (int mb = 0; mb < 2; mb++) {
            red[warp][mb * 16 + g] = p[mb][0];
            red[warp][mb * 16 + g + 8] = p[mb][1];
        }
    }
    __syncthreads();
    if (tid < 128) {
        int row = tid;
        int mwi = row >> 5, rl = row & 31;
        float v = red[mwi * 2][rl] + red[mwi * 2 + 1][rl] + __ldg(ab2);
        int gm = m_base + row;
        if (gm < N_NODES) g_s[gm] = v;
    }
}

// ---------------------------------------------------------------------------
// K2: one CTA per segment (batch sorted -> contiguous ranges). Reads fp16 x.
// ---------------------------------------------------------------------------
__global__ __launch_bounds__(256)
void k2_pool(const int* __restrict__ batch, const int* __restrict__ mask) {
    int seg = blockIdx.x;
    int j = threadIdx.x;

    __shared__ int sh_se[2];
    if (j < 2) {
        int target = seg + j;
        int lo = 0, hi = N_NODES;
        while (lo < hi) {
            int mid = (lo + hi) >> 1;
            if (batch[mid] < target) lo = mid + 1; else hi = mid;
        }
        sh_se[j] = lo;
    }
    __syncthreads();
    int start = sh_se[0], end = sh_se[1];

    float m = -1e30f, z = 0.f, acc = 0.f;
    float S0 = 0.f, S1 = 0.f, S2 = 0.f;
    float c0 = 0.f, c1 = 0.f, c2 = 0.f;

    float si_n = 0.f, xij_n = 0.f;
    int t1_n = 0, t2_n = 0;
    if (start < end) {
        si_n  = __ldg(g_s + start);
        t1_n  = __ldg(mask + (size_t)start * 3 + 1);
        t2_n  = __ldg(mask + (size_t)start * 3 + 2);
        xij_n = __half2float(g_xh[(size_t)start * 256 + j]);
    }

    for (int i = start; i < end; i++) {
        float si = si_n;
        int t1 = t1_n, t2 = t2_n;
        float xij = xij_n;
        int nxt = i + 1;
        if (nxt < end) {
            si_n  = __ldg(g_s + nxt);
            t1_n  = __ldg(mask + (size_t)nxt * 3 + 1);
            t2_n  = __ldg(mask + (size_t)nxt * 3 + 2);
            xij_n = __half2float(g_xh[(size_t)nxt * 256 + j]);
        }
        if (si > m) {
            float sc = __expf(m - si);
            z *= sc; acc *= sc; m = si;
        }
        float e = __expf(si - m);
        z += e;
        acc = fmaf(e, xij, acc);
        if (t1)      { S1 += xij; c1 += 1.f; }
        else if (t2) { S2 += xij; c2 += 1.f; }
        else         { S0 += xij; c0 += 1.f; }
    }

    float count = (float)(end - start);
    size_t base = (size_t)seg * 768;
    g_comb[base + j]       = (S0 + S1 + S2) / count;
    g_comb[base + 256 + j] = acc / z;
    g_S[base + j]       = S0;
    g_S[base + 256 + j] = S1;
    g_S[base + 512 + j] = S2;
    if (j == 0) {
        g_cnt[seg * 3 + 0] = c0;
        g_cnt[seg * 3 + 1] = c1;
        g_cnt[seg * 3 + 2] = c2;
    }
}

// ---------------------------------------------------------------------------
// Small GEMMs, 64(M)x32(N)x16 tiles, 256 threads, 2x4 microtile, register
// double-buffered global loads.
// ---------------------------------------------------------------------------
template <int EPI>
__global__ __launch_bounds__(256)
void gemm_small(const float* __restrict__ B0, const float* __restrict__ B1,
                const float* __restrict__ B2,
                const float* __restrict__ bias0, const float* __restrict__ bias1,
                const float* __restrict__ bias2, float* __restrict__ Cout) {
    constexpr int K   = (EPI == 0) ? 512 : 768;
    constexpr int lda = (EPI == 0) ? 512 : 768;
    constexpr int ldb = (EPI == 1) ? 512 : 256;
    constexpr int ldc = (EPI == 2) ? 768 : ((EPI == 1) ? 512 : 256);
    constexpr int coff = (EPI == 2) ? 512 : 0;

    const float* A = (EPI == 2) ? g_S : ((EPI == 1) ? g_comb : g_h);
    float* C = (EPI == 2) ? g_comb : ((EPI == 1) ? g_h : Cout);

    __shared__ float As[16][64];
    __shared__ float Bs[16][32];
    int tid = threadIdx.x;
    int m_base = blockIdx.y * 64;
    int n_base = blockIdx.x * 32;

    float acc[2][4];
#pragma unroll
    for (int i = 0; i < 2; i++)
#pragma unroll
        for (int j = 0; j < 4; j++) acc[i][j] = 0.f;

    int m0 = (tid >> 3) << 1;
    int j0 = (tid & 7) << 2;

    int am = tid >> 2, ac = (tid & 3) << 2;
    int bk = tid >> 3, bc = (tid & 7) << 2;

    auto brow_ptr = [&](int kk) -> const float* {
        if (EPI == 2) {
            return (kk < 256) ? (B0 + (size_t)kk * ldb)
                 : (kk < 512) ? (B1 + (size_t)(kk - 256) * ldb)
                              : (B2 + (size_t)(kk - 512) * ldb);
        }
        return B0 + (size_t)kk * ldb;
    };

    float4 pa = *(const float4*)(A + (size_t)(m_base + am) * lda + ac);
    float4 pb = make_float4(0.f, 0.f, 0.f, 0.f);
    if (tid < 128) pb = *(const float4*)(brow_ptr(bk) + n_base + bc);

    for (int k0 = 0; k0 < K; k0 += 16) {
        As[ac + 0][am] = pa.x; As[ac + 1][am] = pa.y;
        As[ac + 2][am] = pa.z; As[ac + 3][am] = pa.w;
        if (tid < 128) *(float4*)&Bs[bk][bc] = pb;
        __syncthreads();

        int kn = k0 + 16;
        if (kn < K) {
            pa = *(const float4*)(A + (size_t)(m_base + am) * lda + kn + ac);
            if (tid < 128) pb = *(const float4*)(brow_ptr(kn + bk) + n_base + bc);
        }

#pragma unroll
        for (int k = 0; k < 16; k++) {
            float a0 = As[k][m0], a1 = As[k][m0 + 1];
            float4 bv = *(const float4*)&Bs[k][j0];
            float b[4] = {bv.x, bv.y, bv.z, bv.w};
#pragma unroll
            for (int jj = 0; jj < 4; jj++) {
                acc[0][jj] = fmaf(a0, b[jj], acc[0][jj]);
                acc[1][jj] = fmaf(a1, b[jj], acc[1][jj]);
            }
        }
        __syncthreads();
    }

#pragma unroll
    for (int i = 0; i < 2; i++) {
        int m = m_base + m0 + i;
#pragma unroll
        for (int jj = 0; jj < 4; jj++) {
            int n = n_base + j0 + jj;
            float v = acc[i][jj];
            if (EPI == 0) {
                v += __ldg(bias0 + n);
            } else if (EPI == 1) {
                v += __ldg(bias0 + n);
                v = v / (1.f + __expf(-v));   // silu
            } else {
                v += g_cnt[m * 3 + 0] * __ldg(bias0 + n)
                   + g_cnt[m * 3 + 1] * __ldg(bias1 + n)
                   + g_cnt[m * 3 + 2] * __ldg(bias2 + n);
            }
            C[(size_t)m * ldc + coff + n] = v;
        }
    }
}

// ---------------------------------------------------------------------------
extern "C" void kernel_launch(void* const* d_in, const int* in_sizes, int n_in,
                              void* d_out, int out_size) {
    const float* x    = (const float*)d_in[0];
    const int*   batch = (const int*)d_in[1];
    const int*   mask  = (const int*)d_in[2];
    const float* aw1 = (const float*)d_in[4];
    const float* ab1 = (const float*)d_in[5];
    const float* aw2 = (const float*)d_in[6];
    const float* ab2 = (const float*)d_in[7];
    const float* we  = (const float*)d_in[8];
    const float* be  = (const float*)d_in[9];
    const float* wv  = (const float*)d_in[10];
    const float* bv  = (const float*)d_in[11];
    const float* wp  = (const float*)d_in[12];
    const float* bp  = (const float*)d_in[13];
    const float* w1  = (const float*)d_in[14];
    const float* b1  = (const float*)d_in[15];
    const float* w2  = (const float*)d_in[16];
    const float* b2  = (const float*)d_in[17];

    static bool attr_done = false;
    if (!attr_done) {
        cudaFuncSetAttribute(k1_scores,
                             cudaFuncAttributeMaxDynamicSharedMemorySize, 112640);
        attr_done = true;
    }

    k0_wsplit<<<128, 256>>>(aw1);
    k_convert<<<(N_NODES * 256) / (256 * 8), 256>>>(x);   // 25000 blocks, exact
    k1_scores<<<(N_NODES + 127) / 128, 256, 112640>>>(ab1, aw2, ab2);
    k2_pool<<<NSEG, 256>>>(batch, mask);
    gemm_small<2><<<dim3(8, 16), 256>>>(we, wv, wp, be, bv, bp, nullptr);
    gemm_small<1><<<dim3(16, 16), 256>>>(w1, nullptr, nullptr, b1, nullptr, nullptr, nullptr);
    gemm_small<0><<<dim3(8, 16), 256>>>(w2, nullptr, nullptr, b2, nullptr, nullptr, (float*)d_out);
}

// round 14
// speedup vs baseline: 2.7263x; 1.4064x over previous
#include <cuda_runtime.h>
#include <cuda_fp16.h>
#include <math.h>
#include <stdint.h>

#define N_NODES 200000
#define NSEG 1024
#define KP 40   // smem k-pitch (half elems): 80B rows -> conflict-free ldmatrix

// scratch (device globals: no allocation allowed)
__device__ float g_s[N_NODES];
__device__ float2 g_wt[N_NODES];           // {unnormalized softmax e, type as float}
__device__ float g_zz[NSEG];               // per-segment softmax denom
__device__ float g_S[NSEG * 768];
__device__ float g_comb[NSEG * 768];
__device__ float g_h[NSEG * 512];
__device__ float g_cnt[NSEG * 3];
__device__ __half g_Bh[8 * 5120];          // fp16(aw1), 8 chunk-tiles [n][kin] pitch KP
__device__ __half g_xh[(size_t)N_NODES * 256];  // fp16(x)

__device__ __forceinline__ uint32_t smem_u32(const void* p) {
    uint32_t a;
    asm("{ .reg .u64 t; cvta.to.shared.u64 t, %1; cvt.u32.u64 %0, t; }"
        : "=r"(a) : "l"(p));
    return a;
}
__device__ __forceinline__ void mma16816(float* d, const unsigned* a,
                                         const unsigned* b) {
    asm volatile(
        "mma.sync.aligned.m16n8k16.row.col.f32.f16.f16.f32 "
        "{%0,%1,%2,%3}, {%4,%5,%6,%7}, {%8,%9}, {%0,%1,%2,%3};"
        : "+f"(d[0]), "+f"(d[1]), "+f"(d[2]), "+f"(d[3])
        : "r"(a[0]), "r"(a[1]), "r"(a[2]), "r"(a[3]), "r"(b[0]), "r"(b[1]));
}
__device__ __forceinline__ void ldsm4(unsigned* r, uint32_t addr) {
    asm volatile(
        "ldmatrix.sync.aligned.m8n8.x4.shared.b16 {%0,%1,%2,%3}, [%4];"
        : "=r"(r[0]), "=r"(r[1]), "=r"(r[2]), "=r"(r[3]) : "r"(addr));
}
#define CP_COMMIT() asm volatile("cp.async.commit_group;" ::: "memory")

// ---------------------------------------------------------------------------
// K0: one-time fp16 quantization of aw1 into chunk-tiled [n][kin] images.
// ---------------------------------------------------------------------------
__global__ __launch_bounds__(256)
void k0_wsplit(const float* __restrict__ aw1) {
    int idx = blockIdx.x * 256 + threadIdx.x;   // 0..32767
    int k = idx >> 7, n = idx & 127;
    int chunk = k >> 5, kin = k & 31;
    g_Bh[chunk * 5120 + n * KP + kin] = __float2half_rn(aw1[(size_t)k * 128 + n]);
}

// ---------------------------------------------------------------------------
// KC: x (fp32) -> g_xh (fp16), pure bandwidth kernel, 8 elems/thread.
// ---------------------------------------------------------------------------
__global__ __launch_bounds__(256)
void k_convert(const float* __restrict__ x) {
    size_t i = ((size_t)blockIdx.x * 256 + threadIdx.x) * 8;
    float4 a = *(const float4*)(x + i);
    float4 b = *(const float4*)(x + i + 4);
    __half2 h0 = __floats2half2_rn(a.x, a.y);
    __half2 h1 = __floats2half2_rn(a.z, a.w);
    __half2 h2 = __floats2half2_rn(b.x, b.y);
    __half2 h3 = __floats2half2_rn(b.z, b.w);
    *(uint4*)(g_xh + i) = make_uint4(*(unsigned*)&h0, *(unsigned*)&h1,
                                     *(unsigned*)&h2, *(unsigned*)&h3);
}

// ---------------------------------------------------------------------------
// K1: s[i] = tanh(x[i]@aw1 + ab1) @ aw2 + ab2, tensor-core path. (unchanged)
// ---------------------------------------------------------------------------
__global__ __launch_bounds__(256)
void k1_scores(const float* __restrict__ ab1, const float* __restrict__ aw2,
               const float* __restrict__ ab2) {
    extern __shared__ __align__(16) char smc[];
    __shared__ float red[8][32];

    int tid = threadIdx.x;
    int warp = tid >> 5, lane = tid & 31;
    int g = lane >> 2, tg = lane & 3;
    int warp_m = (warp >> 1) * 32, warp_n = (warp & 1) * 64;
    int m_base = blockIdx.x * 128;
    uint32_t sb = smem_u32(smc);

    int arow = lane & 15, akoff = (lane >> 4) * 8;
    int bnrow = ((lane >> 4) << 3) + (lane & 7), bkoff = ((lane >> 3) & 1) * 8;

    float acc[2][8][4];
#pragma unroll
    for (int a = 0; a < 2; a++)
#pragma unroll
        for (int b = 0; b < 8; b++)
#pragma unroll
            for (int c = 0; c < 4; c++) acc[a][b][c] = 0.f;

    {
        const uint4* src = (const uint4*)g_Bh;
        uint4* dst = (uint4*)(smc + 30720);
#pragma unroll
        for (int i = 0; i < 20; i++) dst[tid + i * 256] = src[tid + i * 256];
    }

    auto copyA = [&](int c, int s) {
        uint32_t stage = sb + s * 10240;
#pragma unroll
        for (int i = 0; i < 2; i++) {
            int o = tid + i * 256;
            int row = o >> 2, q = o & 3;
            int gm = m_base + row;
            const __half* src = g_xh + (size_t)gm * 256 + c * 32 + q * 8;
            uint32_t dst = stage + row * 80 + q * 16;
            int sz = (gm < N_NODES) ? 16 : 0;
            asm volatile("cp.async.cg.shared.global [%0], [%1], 16, %2;"
                         :: "r"(dst), "l"(src), "r"(sz) : "memory");
        }
        CP_COMMIT();
    };

    auto mmaChunk = [&](int c, int s) {
        uint32_t aB = sb + s * 10240;
        uint32_t bB = sb + 30720 + c * 10240;
#pragma unroll
        for (int kb = 0; kb < 2; kb++) {
            unsigned ah[2][4];
            ldsm4(ah[0], aB + (warp_m + arow) * 80 + (kb * 16 + akoff) * 2);
            ldsm4(ah[1], aB + (warp_m + 16 + arow) * 80 + (kb * 16 + akoff) * 2);
#pragma unroll
            for (int nbp = 0; nbp < 4; nbp++) {
                unsigned bb[4];
                ldsm4(bb, bB + (warp_n + nbp * 16 + bnrow) * 80 + (kb * 16 + bkoff) * 2);
#pragma unroll
                for (int mb = 0; mb < 2; mb++) {
                    mma16816(acc[mb][nbp * 2 + 0], ah[mb], bb + 0);
                    mma16816(acc[mb][nbp * 2 + 1], ah[mb], bb + 2);
                }
            }
        }
    };

    copyA(0, 0);
    copyA(1, 1);

#pragma unroll
    for (int c = 0; c < 8; c++) {
        if (c < 7) {
            asm volatile("cp.async.wait_group 1;" ::: "memory");
        } else {
            asm volatile("cp.async.wait_group 0;" ::: "memory");
        }
        __syncthreads();
        if (c < 6) copyA(c + 2, (c + 2) % 3);
        mmaChunk(c, c % 3);
    }

    float p[2][2] = {{0.f, 0.f}, {0.f, 0.f}};
#pragma unroll
    for (int mb = 0; mb < 2; mb++) {
#pragma unroll
        for (int nb = 0; nb < 8; nb++) {
            int n0 = warp_n + nb * 8 + tg * 2;
            float w0 = __ldg(aw2 + n0), w1 = __ldg(aw2 + n0 + 1);
            float bb0 = __ldg(ab1 + n0), bb1 = __ldg(ab1 + n0 + 1);
            p[mb][0] = fmaf(tanhf(acc[mb][nb][0] + bb0), w0, p[mb][0]);
            p[mb][0] = fmaf(tanhf(acc[mb][nb][1] + bb1), w1, p[mb][0]);
            p[mb][1] = fmaf(tanhf(acc[mb][nb][2] + bb0), w0, p[mb][1]);
            p[mb][1] = fmaf(tanhf(acc[mb][nb][3] + bb1), w1, p[mb][1]);
        }
    }
#pragma unroll
    for (int mb = 0; mb < 2; mb++)
#pragma unroll
        for (int h = 0; h < 2; h++) {
            p[mb][h] += __shfl_xor_sync(0xffffffffu, p[mb][h], 1);
            p[mb][h] += __shfl_xor_sync(0xffffffffu, p[mb][h], 2);
        }
    if (tg == 0) {
#pragma unroll
        for (int mb = 0; mb < 2; mb++) {
            red[warp][mb * 16 + g] = p[mb][0];
            red[warp][mb * 16 + g + 8] = p[mb][1];
        }
    }
    __syncthreads();
    if (tid < 128) {
        int row = tid;
        int mwi = row >> 5, rl = row & 31;
        float v = red[mwi * 2][rl] + red[mwi * 2 + 1][rl] + __ldg(ab2);
        int gm = m_base + row;
        if (gm < N_NODES) g_s[gm] = v;
    }
}

// ---------------------------------------------------------------------------
// K2a: per-segment scalar pass on g_s/mask: softmax weights (unnormalized),
// type-as-float, denom z, per-type counts. One CTA per segment.
// ---------------------------------------------------------------------------
__global__ __launch_bounds__(256)
void k2a_coef(const int* __restrict__ batch, const int* __restrict__ mask) {
    __shared__ float rbuf[256];
    __shared__ int sh_se[2];
    int seg = blockIdx.x, tid = threadIdx.x;

    if (tid < 2) {
        int target = seg + tid;
        int lo = 0, hi = N_NODES;
        while (lo < hi) {
            int mid = (lo + hi) >> 1;
            if (batch[mid] < target) lo = mid + 1; else hi = mid;
        }
        sh_se[tid] = lo;
    }
    __syncthreads();
    int start = sh_se[0], end = sh_se[1];

    // max reduce
    float lm = -1e30f;
    for (int i = start + tid; i < end; i += 256) lm = fmaxf(lm, g_s[i]);
    rbuf[tid] = lm;
    __syncthreads();
#pragma unroll
    for (int o = 128; o > 0; o >>= 1) {
        if (tid < o) rbuf[tid] = fmaxf(rbuf[tid], rbuf[tid + o]);
        __syncthreads();
    }
    float m = rbuf[0];
    __syncthreads();

    // e, type, local sums
    float lz = 0.f, l1 = 0.f, l2 = 0.f;
    for (int i = start + tid; i < end; i += 256) {
        float e = __expf(g_s[i] - m);
        lz += e;
        int t1 = __ldg(mask + (size_t)i * 3 + 1);
        int t2 = __ldg(mask + (size_t)i * 3 + 2);
        float tf = t1 ? 1.f : (t2 ? 2.f : 0.f);
        g_wt[i] = make_float2(e, tf);
        if (t1) l1 += 1.f;
        else if (t2) l2 += 1.f;
    }
    // three tree reductions via rbuf
    float z, c1, c2;
    rbuf[tid] = lz; __syncthreads();
#pragma unroll
    for (int o = 128; o > 0; o >>= 1) {
        if (tid < o) rbuf[tid] += rbuf[tid + o];
        __syncthreads();
    }
    z = rbuf[0]; __syncthreads();
    rbuf[tid] = l1; __syncthreads();
#pragma unroll
    for (int o = 128; o > 0; o >>= 1) {
        if (tid < o) rbuf[tid] += rbuf[tid + o];
        __syncthreads();
    }
    c1 = rbuf[0]; __syncthreads();
    rbuf[tid] = l2; __syncthreads();
#pragma unroll
    for (int o = 128; o > 0; o >>= 1) {
        if (tid < o) rbuf[tid] += rbuf[tid + o];
        __syncthreads();
    }
    c2 = rbuf[0];
    if (tid == 0) {
        g_zz[seg] = z;
        float cnt = (float)(end - start);
        g_cnt[seg * 3 + 0] = cnt - c1 - c2;
        g_cnt[seg * 3 + 1] = c1;
        g_cnt[seg * 3 + 2] = c2;
    }
}

// ---------------------------------------------------------------------------
// K2: pooling with precomputed coefs; fp32 x; block-staged coefs in shared;
// dependency-free inner loop (S = total sum; type0 = S - S1 - S2).
// ---------------------------------------------------------------------------
__global__ __launch_bounds__(256)
void k2_pool(const float* __restrict__ x, const int* __restrict__ batch) {
    __shared__ float2 swt[256];
    __shared__ int sh_se[2];
    int seg = blockIdx.x, j = threadIdx.x;

    if (j < 2) {
        int target = seg + j;
        int lo = 0, hi = N_NODES;
        while (lo < hi) {
            int mid = (lo + hi) >> 1;
            if (batch[mid] < target) lo = mid + 1; else hi = mid;
        }
        sh_se[j] = lo;
    }
    __syncthreads();
    int start = sh_se[0], end = sh_se[1];

    float acc = 0.f, S = 0.f, S1 = 0.f, S2 = 0.f;

    for (int blk = start; blk < end; blk += 256) {
        int n = end - blk; if (n > 256) n = 256;
        if (j < n) swt[j] = g_wt[blk + j];
        __syncthreads();
#pragma unroll 4
        for (int u = 0; u < n; u++) {
            float2 c = swt[u];
            float xv = __ldg(x + (size_t)(blk + u) * 256 + j);
            acc = fmaf(c.x, xv, acc);
            S += xv;
            S1 += (c.y == 1.f) ? xv : 0.f;
            S2 += (c.y == 2.f) ? xv : 0.f;
        }
        __syncthreads();
    }

    float z = g_zz[seg];
    float cnt = (float)(end - start);
    size_t base = (size_t)seg * 768;
    g_comb[base + j]       = S / cnt;
    g_comb[base + 256 + j] = acc / z;
    g_S[base + j]       = S - S1 - S2;
    g_S[base + 256 + j] = S1;
    g_S[base + 512 + j] = S2;
}

// ---------------------------------------------------------------------------
// Small GEMMs, 64(M)x32(N)x32(K-step) tiles, 256 threads, 2x4 microtile,
// smem double-buffered: ONE sync per K-iteration (24 iters for K=768).
// ---------------------------------------------------------------------------
template <int EPI>
__global__ __launch_bounds__(256)
void gemm_small(const float* __restrict__ B0, const float* __restrict__ B1,
                const float* __restrict__ B2,
                const float* __restrict__ bias0, const float* __restrict__ bias1,
                const float* __restrict__ bias2, float* __restrict__ Cout) {
    constexpr int K   = (EPI == 0) ? 512 : 768;
    constexpr int lda = (EPI == 0) ? 512 : 768;
    constexpr int ldb = (EPI == 1) ? 512 : 256;
    constexpr int ldc = (EPI == 2) ? 768 : ((EPI == 1) ? 512 : 256);
    constexpr int coff = (EPI == 2) ? 512 : 0;

    const float* A = (EPI == 2) ? g_S : ((EPI == 1) ? g_comb : g_h);
    float* C = (EPI == 2) ? g_comb : ((EPI == 1) ? g_h : Cout);

    __shared__ float As[2][32][64];
    __shared__ float Bs[2][32][32];
    int tid = threadIdx.x;
    int m_base = blockIdx.y * 64;
    int n_base = blockIdx.x * 32;

    float acc[2][4];
#pragma unroll
    for (int i = 0; i < 2; i++)
#pragma unroll
        for (int j = 0; j < 4; j++) acc[i][j] = 0.f;

    int m0 = (tid >> 3) << 1;
    int j0 = (tid & 7) << 2;

    int am = tid >> 2, ac = (tid & 3) << 2;   // A: row am, k cols ac & ac+16
    int bk = tid >> 3, bc = (tid & 7) << 2;   // B: k row bk (0..31), cols bc

    auto brow_ptr = [&](int kk) -> const float* {
        if (EPI == 2) {
            return (kk < 256) ? (B0 + (size_t)kk * ldb)
                 : (kk < 512) ? (B1 + (size_t)(kk - 256) * ldb)
                              : (B2 + (size_t)(kk - 512) * ldb);
        }
        return B0 + (size_t)kk * ldb;
    };

    float4 pa0 = *(const float4*)(A + (size_t)(m_base + am) * lda + ac);
    float4 pa1 = *(const float4*)(A + (size_t)(m_base + am) * lda + ac + 16);
    float4 pb  = *(const float4*)(brow_ptr(bk) + n_base + bc);

    int buf = 0;
    // store k0=0 tile
    As[0][ac + 0][am] = pa0.x; As[0][ac + 1][am] = pa0.y;
    As[0][ac + 2][am] = pa0.z; As[0][ac + 3][am] = pa0.w;
    As[0][ac + 16][am] = pa1.x; As[0][ac + 17][am] = pa1.y;
    As[0][ac + 18][am] = pa1.z; As[0][ac + 19][am] = pa1.w;
    *(float4*)&Bs[0][bk][bc] = pb;
    __syncthreads();

    for (int k0 = 0; k0 < K; k0 += 32) {
        int kn = k0 + 32;
        if (kn < K) {
            pa0 = *(const float4*)(A + (size_t)(m_base + am) * lda + kn + ac);
            pa1 = *(const float4*)(A + (size_t)(m_base + am) * lda + kn + ac + 16);
            pb  = *(const float4*)(brow_ptr(kn + bk) + n_base + bc);
        }

#pragma unroll
        for (int k = 0; k < 32; k++) {
            float a0 = As[buf][k][m0], a1 = As[buf][k][m0 + 1];
            float4 bv = *(const float4*)&Bs[buf][k][j0];
            float b[4] = {bv.x, bv.y, bv.z, bv.w};
#pragma unroll
            for (int jj = 0; jj < 4; jj++) {
                acc[0][jj] = fmaf(a0, b[jj], acc[0][jj]);
                acc[1][jj] = fmaf(a1, b[jj], acc[1][jj]);
            }
        }

        if (kn < K) {
            int nb = buf ^ 1;
            As[nb][ac + 0][am] = pa0.x; As[nb][ac + 1][am] = pa0.y;
            As[nb][ac + 2][am] = pa0.z; As[nb][ac + 3][am] = pa0.w;
            As[nb][ac + 16][am] = pa1.x; As[nb][ac + 17][am] = pa1.y;
            As[nb][ac + 18][am] = pa1.z; As[nb][ac + 19][am] = pa1.w;
            *(float4*)&Bs[nb][bk][bc] = pb;
        }
        __syncthreads();
        buf ^= 1;
    }

#pragma unroll
    for (int i = 0; i < 2; i++) {
        int m = m_base + m0 + i;
#pragma unroll
        for (int jj = 0; jj < 4; jj++) {
            int n = n_base + j0 + jj;
            float v = acc[i][jj];
            if (EPI == 0) {
                v += __ldg(bias0 + n);
            } else if (EPI == 1) {
                v += __ldg(bias0 + n);
                v = v / (1.f + __expf(-v));   // silu
            } else {
                v += g_cnt[m * 3 + 0] * __ldg(bias0 + n)
                   + g_cnt[m * 3 + 1] * __ldg(bias1 + n)
                   + g_cnt[m * 3 + 2] * __ldg(bias2 + n);
            }
            C[(size_t)m * ldc + coff + n] = v;
        }
    }
}

// ---------------------------------------------------------------------------
extern "C" void kernel_launch(void* const* d_in, const int* in_sizes, int n_in,
                              void* d_out, int out_size) {
    const float* x    = (const float*)d_in[0];
    const int*   batch = (const int*)d_in[1];
    const int*   mask  = (const int*)d_in[2];
    const float* aw1 = (const float*)d_in[4];
    const float* ab1 = (const float*)d_in[5];
    const float* aw2 = (const float*)d_in[6];
    const float* ab2 = (const float*)d_in[7];
    const float* we  = (const float*)d_in[8];
    const float* be  = (const float*)d_in[9];
    const float* wv  = (const float*)d_in[10];
    const float* bv  = (const float*)d_in[11];
    const float* wp  = (const float*)d_in[12];
    const float* bp  = (const float*)d_in[13];
    const float* w1  = (const float*)d_in[14];
    const float* b1  = (const float*)d_in[15];
    const float* w2  = (const float*)d_in[16];
    const float* b2  = (const float*)d_in[17];

    static bool attr_done = false;
    if (!attr_done) {
        cudaFuncSetAttribute(k1_scores,
                             cudaFuncAttributeMaxDynamicSharedMemorySize, 112640);
        attr_done = true;
    }

    k0_wsplit<<<128, 256>>>(aw1);
    k_convert<<<(N_NODES * 256) / (256 * 8), 256>>>(x);
    k1_scores<<<(N_NODES + 127) / 128, 256, 112640>>>(ab1, aw2, ab2);
    k2a_coef<<<NSEG, 256>>>(batch, mask);
    k2_pool<<<NSEG, 256>>>(x, batch);
    gemm_small<2><<<dim3(8, 16), 256>>>(we, wv, wp, be, bv, bp, nullptr);
    gemm_small<1><<<dim3(16, 16), 256>>>(w1, nullptr, nullptr, b1, nullptr, nullptr, nullptr);
    gemm_small<0><<<dim3(8, 16), 256>>>(w2, nullptr, nullptr, b2, nullptr, nullptr, (float*)d_out);
}

// round 15
// speedup vs baseline: 2.7496x; 1.0085x over previous
#include <cuda_runtime.h>
#include <cuda_fp16.h>
#include <math.h>
#include <stdint.h>

#define N_NODES 200000
#define NSEG 1024
#define KP 40   // smem k-pitch (half elems): 80B rows -> conflict-free ldmatrix

// scratch (device globals: no allocation allowed)
__device__ float g_s[N_NODES];
__device__ float g_S[NSEG * 768];
__device__ float g_comb[NSEG * 768];
__device__ float g_h[NSEG * 512];
__device__ float g_cnt[NSEG * 3];
__device__ float g_part[4 * NSEG * 512];   // split-K partials (max 8MB)
__device__ __half g_Bh[8 * 5120];          // fp16(aw1), 8 chunk-tiles [n][kin] pitch KP
__device__ __half g_xh[(size_t)N_NODES * 256];  // fp16(x)

__device__ __forceinline__ uint32_t smem_u32(const void* p) {
    uint32_t a;
    asm("{ .reg .u64 t; cvta.to.shared.u64 t, %1; cvt.u32.u64 %0, t; }"
        : "=r"(a) : "l"(p));
    return a;
}
__device__ __forceinline__ void mma16816(float* d, const unsigned* a,
                                         const unsigned* b) {
    asm volatile(
        "mma.sync.aligned.m16n8k16.row.col.f32.f16.f16.f32 "
        "{%0,%1,%2,%3}, {%4,%5,%6,%7}, {%8,%9}, {%0,%1,%2,%3};"
        : "+f"(d[0]), "+f"(d[1]), "+f"(d[2]), "+f"(d[3])
        : "r"(a[0]), "r"(a[1]), "r"(a[2]), "r"(a[3]), "r"(b[0]), "r"(b[1]));
}
__device__ __forceinline__ void ldsm4(unsigned* r, uint32_t addr) {
    asm volatile(
        "ldmatrix.sync.aligned.m8n8.x4.shared.b16 {%0,%1,%2,%3}, [%4];"
        : "=r"(r[0]), "=r"(r[1]), "=r"(r[2]), "=r"(r[3]) : "r"(addr));
}
#define CP_COMMIT() asm volatile("cp.async.commit_group;" ::: "memory")

// ---------------------------------------------------------------------------
// K0: one-time fp16 quantization of aw1 into chunk-tiled [n][kin] images.
// ---------------------------------------------------------------------------
__global__ __launch_bounds__(256)
void k0_wsplit(const float* __restrict__ aw1) {
    int idx = blockIdx.x * 256 + threadIdx.x;
    int k = idx >> 7, n = idx & 127;
    int chunk = k >> 5, kin = k & 31;
    g_Bh[chunk * 5120 + n * KP + kin] = __float2half_rn(aw1[(size_t)k * 128 + n]);
}

// ---------------------------------------------------------------------------
// KC: x (fp32) -> g_xh (fp16), pure bandwidth kernel, 8 elems/thread.
// ---------------------------------------------------------------------------
__global__ __launch_bounds__(256)
void k_convert(const float* __restrict__ x) {
    size_t i = ((size_t)blockIdx.x * 256 + threadIdx.x) * 8;
    float4 a = *(const float4*)(x + i);
    float4 b = *(const float4*)(x + i + 4);
    __half2 h0 = __floats2half2_rn(a.x, a.y);
    __half2 h1 = __floats2half2_rn(a.z, a.w);
    __half2 h2 = __floats2half2_rn(b.x, b.y);
    __half2 h3 = __floats2half2_rn(b.z, b.w);
    *(uint4*)(g_xh + i) = make_uint4(*(unsigned*)&h0, *(unsigned*)&h1,
                                     *(unsigned*)&h2, *(unsigned*)&h3);
}

// ---------------------------------------------------------------------------
// K1: s[i] = tanh(x[i]@aw1 + ab1) @ aw2 + ab2, tensor-core path. (unchanged)
// ---------------------------------------------------------------------------
__global__ __launch_bounds__(256)
void k1_scores(const float* __restrict__ ab1, const float* __restrict__ aw2,
               const float* __restrict__ ab2) {
    extern __shared__ __align__(16) char smc[];
    __shared__ float red[8][32];

    int tid = threadIdx.x;
    int warp = tid >> 5, lane = tid & 31;
    int g = lane >> 2, tg = lane & 3;
    int warp_m = (warp >> 1) * 32, warp_n = (warp & 1) * 64;
    int m_base = blockIdx.x * 128;
    uint32_t sb = smem_u32(smc);

    int arow = lane & 15, akoff = (lane >> 4) * 8;
    int bnrow = ((lane >> 4) << 3) + (lane & 7), bkoff = ((lane >> 3) & 1) * 8;

    float acc[2][8][4];
#pragma unroll
    for (int a = 0; a < 2; a++)
#pragma unroll
        for (int b = 0; b < 8; b++)
#pragma unroll
            for (int c = 0; c < 4; c++) acc[a][b][c] = 0.f;

    {
        const uint4* src = (const uint4*)g_Bh;
        uint4* dst = (uint4*)(smc + 30720);
#pragma unroll
        for (int i = 0; i < 20; i++) dst[tid + i * 256] = src[tid + i * 256];
    }

    auto copyA = [&](int c, int s) {
        uint32_t stage = sb + s * 10240;
#pragma unroll
        for (int i = 0; i < 2; i++) {
            int o = tid + i * 256;
            int row = o >> 2, q = o & 3;
            int gm = m_base + row;
            const __half* src = g_xh + (size_t)gm * 256 + c * 32 + q * 8;
            uint32_t dst = stage + row * 80 + q * 16;
            int sz = (gm < N_NODES) ? 16 : 0;
            asm volatile("cp.async.cg.shared.global [%0], [%1], 16, %2;"
                         :: "r"(dst), "l"(src), "r"(sz) : "memory");
        }
        CP_COMMIT();
    };

    auto mmaChunk = [&](int c, int s) {
        uint32_t aB = sb + s * 10240;
        uint32_t bB = sb + 30720 + c * 10240;
#pragma unroll
        for (int kb = 0; kb < 2; kb++) {
            unsigned ah[2][4];
            ldsm4(ah[0], aB + (warp_m + arow) * 80 + (kb * 16 + akoff) * 2);
            ldsm4(ah[1], aB + (warp_m + 16 + arow) * 80 + (kb * 16 + akoff) * 2);
#pragma unroll
            for (int nbp = 0; nbp < 4; nbp++) {
                unsigned bb[4];
                ldsm4(bb, bB + (warp_n + nbp * 16 + bnrow) * 80 + (kb * 16 + bkoff) * 2);
#pragma unroll
                for (int mb = 0; mb < 2; mb++) {
                    mma16816(acc[mb][nbp * 2 + 0], ah[mb], bb + 0);
                    mma16816(acc[mb][nbp * 2 + 1], ah[mb], bb + 2);
                }
            }
        }
    };

    copyA(0, 0);
    copyA(1, 1);

#pragma unroll
    for (int c = 0; c < 8; c++) {
        if (c < 7) {
            asm volatile("cp.async.wait_group 1;" ::: "memory");
        } else {
            asm volatile("cp.async.wait_group 0;" ::: "memory");
        }
        __syncthreads();
        if (c < 6) copyA(c + 2, (c + 2) % 3);
        mmaChunk(c, c % 3);
    }

    float p[2][2] = {{0.f, 0.f}, {0.f, 0.f}};
#pragma unroll
    for (int mb = 0; mb < 2; mb++) {
#pragma unroll
        for (int nb = 0; nb < 8; nb++) {
            int n0 = warp_n + nb * 8 + tg * 2;
            float w0 = __ldg(aw2 + n0), w1 = __ldg(aw2 + n0 + 1);
            float bb0 = __ldg(ab1 + n0), bb1 = __ldg(ab1 + n0 + 1);
            p[mb][0] = fmaf(tanhf(acc[mb][nb][0] + bb0), w0, p[mb][0]);
            p[mb][0] = fmaf(tanhf(acc[mb][nb][1] + bb1), w1, p[mb][0]);
            p[mb][1] = fmaf(tanhf(acc[mb][nb][2] + bb0), w0, p[mb][1]);
            p[mb][1] = fmaf(tanhf(acc[mb][nb][3] + bb1), w1, p[mb][1]);
        }
    }
#pragma unroll
    for (int mb = 0; mb < 2; mb++)
#pragma unroll
        for (int h = 0; h < 2; h++) {
            p[mb][h] += __shfl_xor_sync(0xffffffffu, p[mb][h], 1);
            p[mb][h] += __shfl_xor_sync(0xffffffffu, p[mb][h], 2);
        }
    if (tg == 0) {
#pragma unroll
        for (int mb = 0; mb < 2; mb++) {
            red[warp][mb * 16 + g] = p[mb][0];
            red[warp][mb * 16 + g + 8] = p[mb][1];
        }
    }
    __syncthreads();
    if (tid < 128) {
        int row = tid;
        int mwi = row >> 5, rl = row & 31;
        float v = red[mwi * 2][rl] + red[mwi * 2 + 1][rl] + __ldg(ab2);
        int gm = m_base + row;
        if (gm < N_NODES) g_s[gm] = v;
    }
}

// ---------------------------------------------------------------------------
// K2: fused pooling. Prologue (per segment): max, z, counts from g_s/mask.
// Main loop: stage 256 {e,type} coefs in smem (computed on the fly),
// dependency-free fp32 x accumulation.
// ---------------------------------------------------------------------------
__global__ __launch_bounds__(256)
void k2_pool(const float* __restrict__ x, const int* __restrict__ batch,
             const int* __restrict__ mask) {
    __shared__ float rbuf[256];
    __shared__ float2 swt[256];
    __shared__ int sh_se[2];
    int seg = blockIdx.x, j = threadIdx.x;

    if (j < 2) {
        int target = seg + j;
        int lo = 0, hi = N_NODES;
        while (lo < hi) {
            int mid = (lo + hi) >> 1;
            if (batch[mid] < target) lo = mid + 1; else hi = mid;
        }
        sh_se[j] = lo;
    }
    __syncthreads();
    int start = sh_se[0], end = sh_se[1];

    // prologue pass 1: segment max of s
    float lm = -1e30f;
    for (int i = start + j; i < end; i += 256) lm = fmaxf(lm, g_s[i]);
    rbuf[j] = lm;
    __syncthreads();
#pragma unroll
    for (int o = 128; o > 0; o >>= 1) {
        if (j < o) rbuf[j] = fmaxf(rbuf[j], rbuf[j + o]);
        __syncthreads();
    }
    float m = rbuf[0];
    __syncthreads();

    // prologue pass 2: z and type counts
    float lz = 0.f, l1 = 0.f, l2 = 0.f;
    for (int i = start + j; i < end; i += 256) {
        lz += __expf(g_s[i] - m);
        int t1 = __ldg(mask + (size_t)i * 3 + 1);
        int t2 = __ldg(mask + (size_t)i * 3 + 2);
        if (t1) l1 += 1.f;
        else if (t2) l2 += 1.f;
    }
    float z, c1, c2;
    rbuf[j] = lz; __syncthreads();
#pragma unroll
    for (int o = 128; o > 0; o >>= 1) {
        if (j < o) rbuf[j] += rbuf[j + o];
        __syncthreads();
    }
    z = rbuf[0]; __syncthreads();
    rbuf[j] = l1; __syncthreads();
#pragma unroll
    for (int o = 128; o > 0; o >>= 1) {
        if (j < o) rbuf[j] += rbuf[j + o];
        __syncthreads();
    }
    c1 = rbuf[0]; __syncthreads();
    rbuf[j] = l2; __syncthreads();
#pragma unroll
    for (int o = 128; o > 0; o >>= 1) {
        if (j < o) rbuf[j] += rbuf[j + o];
        __syncthreads();
    }
    c2 = rbuf[0];
    if (j == 0) {
        float cnt = (float)(end - start);
        g_cnt[seg * 3 + 0] = cnt - c1 - c2;
        g_cnt[seg * 3 + 1] = c1;
        g_cnt[seg * 3 + 2] = c2;
    }
    __syncthreads();

    // main pooling loop
    float acc = 0.f, S = 0.f, S1 = 0.f, S2 = 0.f;
    for (int blk = start; blk < end; blk += 256) {
        int n = end - blk; if (n > 256) n = 256;
        if (j < n) {
            int i = blk + j;
            float e = __expf(g_s[i] - m);
            int t1 = __ldg(mask + (size_t)i * 3 + 1);
            int t2 = __ldg(mask + (size_t)i * 3 + 2);
            float tf = t1 ? 1.f : (t2 ? 2.f : 0.f);
            swt[j] = make_float2(e, tf);
        }
        __syncthreads();
#pragma unroll 4
        for (int u = 0; u < n; u++) {
            float2 c = swt[u];
            float xv = __ldg(x + (size_t)(blk + u) * 256 + j);
            acc = fmaf(c.x, xv, acc);
            S += xv;
            S1 += (c.y == 1.f) ? xv : 0.f;
            S2 += (c.y == 2.f) ? xv : 0.f;
        }
        __syncthreads();
    }

    float cnt = (float)(end - start);
    size_t base = (size_t)seg * 768;
    g_comb[base + j]       = S / cnt;
    g_comb[base + 256 + j] = acc / z;
    g_S[base + j]       = S - S1 - S2;
    g_S[base + 256 + j] = S1;
    g_S[base + 512 + j] = S2;
}

// ---------------------------------------------------------------------------
// Split-K small GEMM partials: 64(M)x32(N) tiles, K-slice per blockIdx.z,
// double-buffered k32, NO bias (applied in epilogue). Writes g_part.
// ---------------------------------------------------------------------------
template <int EPI>
__global__ __launch_bounds__(256)
void gemm_part(const float* __restrict__ B0, const float* __restrict__ B1,
               const float* __restrict__ B2) {
    constexpr int N   = (EPI == 1) ? 512 : 256;
    constexpr int KS  = (EPI == 0) ? 128 : 192;   // K-slice length
    constexpr int lda = (EPI == 0) ? 512 : 768;
    constexpr int ldb = (EPI == 1) ? 512 : 256;

    const float* A = (EPI == 2) ? g_S : ((EPI == 1) ? g_comb : g_h);
    int ksplit = blockIdx.z;
    int koff = ksplit * KS;
    float* C = g_part + (size_t)ksplit * NSEG * N;

    __shared__ float As[2][32][64];
    __shared__ float Bs[2][32][32];
    int tid = threadIdx.x;
    int m_base = blockIdx.y * 64;
    int n_base = blockIdx.x * 32;

    float acc[2][4];
#pragma unroll
    for (int i = 0; i < 2; i++)
#pragma unroll
        for (int j = 0; j < 4; j++) acc[i][j] = 0.f;

    int m0 = (tid >> 3) << 1;
    int j0 = (tid & 7) << 2;

    int am = tid >> 2, ac = (tid & 3) << 2;
    int bk = tid >> 3, bc = (tid & 7) << 2;

    auto brow_ptr = [&](int kk) -> const float* {
        if (EPI == 2) {
            return (kk < 256) ? (B0 + (size_t)kk * ldb)
                 : (kk < 512) ? (B1 + (size_t)(kk - 256) * ldb)
                              : (B2 + (size_t)(kk - 512) * ldb);
        }
        return B0 + (size_t)kk * ldb;
    };

    float4 pa0 = *(const float4*)(A + (size_t)(m_base + am) * lda + koff + ac);
    float4 pa1 = *(const float4*)(A + (size_t)(m_base + am) * lda + koff + ac + 16);
    float4 pb  = *(const float4*)(brow_ptr(koff + bk) + n_base + bc);

    int buf = 0;
    As[0][ac + 0][am] = pa0.x; As[0][ac + 1][am] = pa0.y;
    As[0][ac + 2][am] = pa0.z; As[0][ac + 3][am] = pa0.w;
    As[0][ac + 16][am] = pa1.x; As[0][ac + 17][am] = pa1.y;
    As[0][ac + 18][am] = pa1.z; As[0][ac + 19][am] = pa1.w;
    *(float4*)&Bs[0][bk][bc] = pb;
    __syncthreads();

    for (int k0 = 0; k0 < KS; k0 += 32) {
        int kn = k0 + 32;
        if (kn < KS) {
            pa0 = *(const float4*)(A + (size_t)(m_base + am) * lda + koff + kn + ac);
            pa1 = *(const float4*)(A + (size_t)(m_base + am) * lda + koff + kn + ac + 16);
            pb  = *(const float4*)(brow_ptr(koff + kn + bk) + n_base + bc);
        }

#pragma unroll
        for (int k = 0; k < 32; k++) {
            float a0 = As[buf][k][m0], a1 = As[buf][k][m0 + 1];
            float4 bv = *(const float4*)&Bs[buf][k][j0];
            float b[4] = {bv.x, bv.y, bv.z, bv.w};
#pragma unroll
            for (int jj = 0; jj < 4; jj++) {
                acc[0][jj] = fmaf(a0, b[jj], acc[0][jj]);
                acc[1][jj] = fmaf(a1, b[jj], acc[1][jj]);
            }
        }

        if (kn < KS) {
            int nb = buf ^ 1;
            As[nb][ac + 0][am] = pa0.x; As[nb][ac + 1][am] = pa0.y;
            As[nb][ac + 2][am] = pa0.z; As[nb][ac + 3][am] = pa0.w;
            As[nb][ac + 16][am] = pa1.x; As[nb][ac + 17][am] = pa1.y;
            As[nb][ac + 18][am] = pa1.z; As[nb][ac + 19][am] = pa1.w;
            *(float4*)&Bs[nb][bk][bc] = pb;
        }
        __syncthreads();
        buf ^= 1;
    }

#pragma unroll
    for (int i = 0; i < 2; i++) {
        int m = m_base + m0 + i;
#pragma unroll
        for (int jj = 0; jj < 4; jj++) {
            int n = n_base + j0 + jj;
            C[(size_t)m * N + n] = acc[i][jj];
        }
    }
}

// ---------------------------------------------------------------------------
// Split-K epilogue: sum 4 partials + bias (+silu / +count*bias), write dest.
// ---------------------------------------------------------------------------
template <int EPI>
__global__ __launch_bounds__(256)
void gemm_epi(const float* __restrict__ bias0, const float* __restrict__ bias1,
              const float* __restrict__ bias2, float* __restrict__ Cout) {
    constexpr int N = (EPI == 1) ? 512 : 256;
    int idx = blockIdx.x * 256 + threadIdx.x;   // covers NSEG*N
    int m = idx / N, n = idx - m * N;
    float v = g_part[idx] + g_part[idx + NSEG * N] +
              g_part[idx + 2 * NSEG * N] + g_part[idx + 3 * NSEG * N];
    if (EPI == 0) {
        Cout[idx] = v + __ldg(bias0 + n);
    } else if (EPI == 1) {
        v += __ldg(bias0 + n);
        g_h[idx] = v / (1.f + __expf(-v));
    } else {
        v += g_cnt[m * 3 + 0] * __ldg(bias0 + n)
           + g_cnt[m * 3 + 1] * __ldg(bias1 + n)
           + g_cnt[m * 3 + 2] * __ldg(bias2 + n);
        g_comb[(size_t)m * 768 + 512 + n] = v;
    }
}

// ---------------------------------------------------------------------------
extern "C" void kernel_launch(void* const* d_in, const int* in_sizes, int n_in,
                              void* d_out, int out_size) {
    const float* x    = (const float*)d_in[0];
    const int*   batch = (const int*)d_in[1];
    const int*   mask  = (const int*)d_in[2];
    const float* aw1 = (const float*)d_in[4];
    const float* ab1 = (const float*)d_in[5];
    const float* aw2 = (const float*)d_in[6];
    const float* ab2 = (const float*)d_in[7];
    const float* we  = (const float*)d_in[8];
    const float* be  = (const float*)d_in[9];
    const float* wv  = (const float*)d_in[10];
    const float* bv  = (const float*)d_in[11];
    const float* wp  = (const float*)d_in[12];
    const float* bp  = (const float*)d_in[13];
    const float* w1  = (const float*)d_in[14];
    const float* b1  = (const float*)d_in[15];
    const float* w2  = (const float*)d_in[16];
    const float* b2  = (const float*)d_in[17];

    static bool attr_done = false;
    if (!attr_done) {
        cudaFuncSetAttribute(k1_scores,
                             cudaFuncAttributeMaxDynamicSharedMemorySize, 112640);
        attr_done = true;
    }

    k0_wsplit<<<128, 256>>>(aw1);
    k_convert<<<(N_NODES * 256) / (256 * 8), 256>>>(x);
    k1_scores<<<(N_NODES + 127) / 128, 256, 112640>>>(ab1, aw2, ab2);
    k2_pool<<<NSEG, 256>>>(x, batch, mask);

    gemm_part<2><<<dim3(8, 16, 4), 256>>>(we, wv, wp);
    gemm_epi<2><<<NSEG * 256 / 256, 256>>>(be, bv, bp, nullptr);
    gemm_part<1><<<dim3(16, 16, 4), 256>>>(w1, nullptr, nullptr);
    gemm_epi<1><<<NSEG * 512 / 256, 256>>>(b1, nullptr, nullptr, nullptr);
    gemm_part<0><<<dim3(8, 16, 4), 256>>>(w2, nullptr, nullptr);
    gemm_epi<0><<<NSEG * 256 / 256, 256>>>(b2, nullptr, nullptr, (float*)d_out);
}